// round 12
// baseline (speedup 1.0000x reference)
#include <cuda_runtime.h>
#include <cstdint>

#define NB 4
#define CIN 64
#define COUT3 192
#define LL 129
#define POSN 33024
#define NN2 16512
#define NHEAD 8
#define NBINS 16257
#define PLANE 65536

// ------------------------- device scratch (no allocation) -------------------------
__device__ float  g_qkv [NB*COUT3*PLANE];
__device__ float  g_qkv2[NB*COUT3*PLANE];
__device__ float2 g_rowA[(long)12*256*LL*64];     // [tb][y][k][64ch] complex
__device__ float  g_freq[(long)12*POSN*128];      // [tb][pos][re64|im64]
__device__ float  g_pack[(long)12*NHEAD*32*NN2];  // [tb][h][j][n]
__device__ float  g_opack[(long)NB*NHEAD*32*NN2];
__device__ float  g_ofreq[(long)NB*POSN*128];
__device__ float2 g_backT[(long)NB*256*LL*64];    // [b][y][k][64ch] complex
__device__ float  g_spat[(long)NB*CIN*PLANE];
__device__ float  g_gram[NB*NHEAD*32*32];
__device__ float  g_nrm [NB*NHEAD*64];
__device__ float  g_attn[NB*NHEAD*32*32];
__device__ int    g_hist[NBINS];
__device__ int    g_off [NBINS];
__device__ int    g_idx [POSN];

// ------------------------- helpers -------------------------
__device__ __forceinline__ float2 cmul(float2 a, float2 b){
    return make_float2(a.x*b.x - a.y*b.y, a.x*b.y + a.y*b.x);
}

// packed f32x2 helpers (base sm_100+ PTX; NOT an "a"-gated feature)
__device__ __forceinline__ unsigned long long pack2(float lo, float hi){
    unsigned long long d;
    asm("mov.b64 %0, {%1, %2};" : "=l"(d) : "f"(lo), "f"(hi));
    return d;
}
__device__ __forceinline__ unsigned long long pack2b(float v){
    unsigned long long d;
    asm("mov.b64 %0, {%1, %1};" : "=l"(d) : "f"(v));
    return d;
}
__device__ __forceinline__ void ffma2(unsigned long long& d, unsigned long long a, unsigned long long b){
    asm("fma.rn.f32x2 %0, %1, %2, %0;" : "+l"(d) : "l"(a), "l"(b));
}
__device__ __forceinline__ float2 unpack2(unsigned long long v){
    float2 r;
    asm("mov.b64 {%0, %1}, %2;" : "=f"(r.x), "=f"(r.y) : "l"(v));
    return r;
}

// 16-point radix-2 DIT FFT fully in registers. sgn=-1 forward, +1 inverse.
__device__ __forceinline__ void fft16r(float2* r, float sgn){
    float2 t;
#define SWP(a,b) { t=r[a]; r[a]=r[b]; r[b]=t; }
    SWP(1,8) SWP(2,4) SWP(3,12) SWP(5,10) SWP(7,14) SWP(11,13)
#undef SWP
    const float C[8] = {1.f, 0.92387953251f, 0.70710678119f, 0.38268343236f,
                        0.f, -0.38268343236f, -0.70710678119f, -0.92387953251f};
    const float S[8] = {0.f, 0.38268343236f, 0.70710678119f, 0.92387953251f,
                        1.f, 0.92387953251f, 0.70710678119f, 0.38268343236f};
#pragma unroll
    for (int s = 0; s < 4; s++){
        int half = 1 << s;
#pragma unroll
        for (int k = 0; k < 8; k++){
            int j = k & (half-1);
            int base = ((k>>s)<<(s+1)) + j;
            int m = j << (3-s);
            float2 w = make_float2(C[m], sgn*S[m]);
            float2 a = r[base];
            float2 b = cmul(r[base+half], w);
            r[base]      = make_float2(a.x+b.x, a.y+b.y);
            r[base+half] = make_float2(a.x-b.x, a.y-b.y);
        }
    }
}

__device__ __forceinline__ void build_tw256(float2* tw, float sgn, int tid){
    float ang = sgn * 6.283185307179586f * (float)tid / 256.0f;
    float s, c; sincosf(ang, &s, &c);
    tw[tid] = make_float2(c, s);
}

// ------------------------- permutation -------------------------
__global__ void k_zero(){
    int i = blockIdx.x * 256 + threadIdx.x;
    if (i < NBINS) g_hist[i] = 0;
    if (i < 32*1024) g_gram[i] = 0.f;
    if (i < 32*64) g_nrm[i] = 0.f;
}
__global__ void k_hist(){
    int j = blockIdx.x * 256 + threadIdx.x;
    if (j < POSN){
        int r = j / LL, l = j % LL;
        int m = (r < 128) ? r : 255 - r;
        atomicAdd(&g_hist[m * l], 1);
    }
}
__global__ void k_scan(){
    __shared__ int part[256];
    int tid = threadIdx.x;
    int s = 0;
    for (int i = 0; i < 64; i++){
        int K = tid * 64 + i;
        if (K < NBINS) s += g_hist[K];
    }
    part[tid] = s;
    __syncthreads();
    if (tid == 0){
        int run = 0;
        for (int i = 0; i < 256; i++){ int t = part[i]; part[i] = run; run += t; }
    }
    __syncthreads();
    int run = part[tid];
    for (int i = 0; i < 64; i++){
        int K = tid * 64 + i;
        if (K < NBINS){ g_off[K] = run; run += g_hist[K]; }
    }
}
__global__ void k_fill(){
    int K = blockIdx.x * 256 + threadIdx.x;
    if (K >= NBINS) return;
    int o = g_off[K];
    if (K == 0){
        for (int l = 0; l <= 128; l++) g_idx[o++] = l;
        for (int r = 1; r <= 254; r++) g_idx[o++] = r * LL;
        for (int l = 0; l <= 128; l++) g_idx[o++] = 255 * LL + l;
    } else {
        for (int v = 1; v <= 127; v++)
            if (K % v == 0){ int l = K / v; if (l <= 128) g_idx[o++] = v * LL + l; }
        for (int v = 127; v >= 1; v--)
            if (K % v == 0){ int l = K / v; if (l <= 128) g_idx[o++] = (255 - v) * LL + l; }
    }
}

// ------------------------- 1x1 conv (register-tiled GEMM, f32x2 + LDS.128) -------------------------
template<int OC>
__device__ __forceinline__ void conv_body(const float* __restrict__ x,
                                          const float* __restrict__ w,
                                          float* __restrict__ out){
    __shared__ float xS[8][128];
    __shared__ float wS[8][64];
    int p0 = blockIdx.x * 128;
    int og = blockIdx.y * 64;
    int b = p0 / PLANE; int pp = p0 % PLANE;
    int tid = threadIdx.x;
    int tx = tid & 15, ty = tid >> 4;
    unsigned long long acc[4][4];
    #pragma unroll
    for (int i = 0; i < 4; i++)
        #pragma unroll
        for (int j = 0; j < 4; j++) acc[i][j] = 0ull;
    for (int c0 = 0; c0 < 64; c0 += 8){
        #pragma unroll
        for (int k = 0; k < 4; k++){
            int i = tid + k * 256;
            int cc = i >> 7, px = i & 127;
            xS[cc][px] = x[(long)(b * CIN + c0 + cc) * PLANE + pp + px];
        }
        #pragma unroll
        for (int k = 0; k < 2; k++){
            int i = tid + k * 256;
            int cc = i >> 6, oo = i & 63;
            wS[cc][oo] = w[(og + oo) * CIN + c0 + cc];
        }
        __syncthreads();
        #pragma unroll
        for (int cc = 0; cc < 8; cc++){
            float4 wv = *(const float4*)&wS[cc][ty * 4];          // 1x LDS.128
            unsigned long long wr2[4];
            wr2[0] = pack2b(wv.x); wr2[1] = pack2b(wv.y);
            wr2[2] = pack2b(wv.z); wr2[3] = pack2b(wv.w);
            float4 v0 = *(const float4*)&xS[cc][tx * 8];          // 2x LDS.128
            float4 v1 = *(const float4*)&xS[cc][tx * 8 + 4];
            unsigned long long xr2[4];
            xr2[0] = pack2(v0.x, v0.y); xr2[1] = pack2(v0.z, v0.w);
            xr2[2] = pack2(v1.x, v1.y); xr2[3] = pack2(v1.z, v1.w);
            #pragma unroll
            for (int i = 0; i < 4; i++)
                #pragma unroll
                for (int j = 0; j < 4; j++) ffma2(acc[i][j], wr2[i], xr2[j]);
        }
        __syncthreads();
    }
    #pragma unroll
    for (int i = 0; i < 4; i++){
        int o = og + ty * 4 + i;
        float* dst = out + (long)(b * OC + o) * PLANE + pp + tx * 8;
        #pragma unroll
        for (int j = 0; j < 4; j++) *(float2*)(dst + 2 * j) = unpack2(acc[i][j]);
    }
}
__global__ void __launch_bounds__(256) k_convqkv(const float* __restrict__ x, const float* __restrict__ w){
    conv_body<COUT3>(x, w, g_qkv);
}
__global__ void __launch_bounds__(256) k_convproj(const float* __restrict__ w, float* __restrict__ out){
    conv_body<CIN>(g_spat, w, out);
}

// ------------------------- 3x3 depthwise conv -------------------------
__global__ void __launch_bounds__(256) k_dwconv(const float* __restrict__ wdw){
    __shared__ float sm[18][258];
    int bc = blockIdx.y;
    int ch = bc % COUT3;
    int y0 = blockIdx.x * 16;
    int tid = threadIdx.x;
    const float* src = g_qkv + (long)bc * PLANE;
    for (int i = tid; i < 18 * 258; i += 256){
        int r = i / 258, cc = i % 258;
        int gy = y0 + r - 1, gx = cc - 1;
        float v = 0.f;
        if ((unsigned)gy < 256u && (unsigned)gx < 256u) v = src[gy * 256 + gx];
        sm[r][cc] = v;
    }
    float w[9];
    #pragma unroll
    for (int i = 0; i < 9; i++) w[i] = wdw[ch * 9 + i];
    __syncthreads();
    int x = tid;
    float* dst = g_qkv2 + (long)bc * PLANE;
    for (int yy = 0; yy < 16; yy++){
        float a = 0.f;
        #pragma unroll
        for (int dy = 0; dy < 3; dy++)
            #pragma unroll
            for (int dx = 0; dx < 3; dx++)
                a += w[dy * 3 + dx] * sm[yy + dy][x + dx];
        dst[(y0 + yy) * 256 + x] = a;
    }
}

// ------------------------- row rfft (along x), channel-paired, 16x16 -------------------------
__global__ void __launch_bounds__(256) k_rowfft(){
    __shared__ float2 zbuf[16*257];
    __shared__ float2 tw[256];
    int tid = threadIdx.x;
    int by = blockIdx.y; int b = by >> 8, y = by & 255;
    int ch0 = blockIdx.x * 32;
    build_tw256(tw, -1.f, tid);
    int f = tid >> 4, bc = tid & 15;
    const float* re = g_qkv2 + (long)(b * COUT3 + ch0 + 2*f) * PLANE + y * 256;
    const float* im = re + PLANE;
    float2 r[16];
#pragma unroll
    for (int a = 0; a < 16; a++){ int x = a*16 + bc; r[a] = make_float2(re[x], im[x]); }
    __syncthreads();                 // tw ready
    fft16r(r, -1.f);
#pragma unroll
    for (int c = 0; c < 16; c++) zbuf[(f*16 + c)*16 + bc] = cmul(r[c], tw[bc*c]);
    __syncthreads();
    int c2 = tid & 15;
    float2 q[16];
#pragma unroll
    for (int b2 = 0; b2 < 16; b2++) q[b2] = zbuf[(f*16 + c2)*16 + b2];
    __syncthreads();                 // before re-using zbuf with stride 257
    fft16r(q, -1.f);
#pragma unroll
    for (int d = 0; d < 16; d++) zbuf[f*257 + c2 + 16*d] = q[d];
    __syncthreads();
    int t = ch0 >> 6, cb = ch0 & 63;
    long base = (((long)(t*NB + b) * 256 + y) * LL) * 64 + cb;
    for (int i = tid; i < 16*129; i += 256){
        int k = i >> 4, p = i & 15;
        float2 Zk = zbuf[p*257 + k];
        float2 Zm = zbuf[p*257 + ((256 - k) & 255)];
        float4 v = make_float4(0.5f*(Zk.x + Zm.x), 0.5f*(Zk.y - Zm.y),
                               0.5f*(Zk.y + Zm.y), 0.5f*(Zm.x - Zk.x));
        *(float4*)(g_rowA + base + (long)k*64 + 2*p) = v;
    }
}

// ------------------------- column FFT (along y), 16x16 -------------------------
__global__ void __launch_bounds__(256) k_colfft(){
    __shared__ float2 zbuf[4096];
    __shared__ float2 tw[256];
    int tid = threadIdx.x;
    int gy = blockIdx.y; int tb = gy / LL, kx = gy - tb*LL;
    int cb = blockIdx.x * 16;
    build_tw256(tw, -1.f, tid);
    int bc = tid >> 4, ch = tid & 15;
    const float2* src = g_rowA + ((long)tb*256*LL + kx) * 64 + cb + ch;
    float2 r[16];
#pragma unroll
    for (int a = 0; a < 16; a++) r[a] = src[(long)(a*16 + bc) * LL * 64];
    __syncthreads();
    fft16r(r, -1.f);
#pragma unroll
    for (int c = 0; c < 16; c++) zbuf[(ch*16 + c)*16 + bc] = cmul(r[c], tw[bc*c]);
    __syncthreads();
    int c2 = tid >> 4, ch2 = tid & 15;
    float2 q[16];
#pragma unroll
    for (int b2 = 0; b2 < 16; b2++) q[b2] = zbuf[(ch2*16 + c2)*16 + b2];
    fft16r(q, -1.f);
    const float sc = 1.f/256.f;
    long ob = (long)tb*POSN*128 + (long)kx*128 + cb + ch2;
#pragma unroll
    for (int d = 0; d < 16; d++){
        int ky = c2 + 16*d;
        float* o = g_freq + ob + (long)ky*LL*128;
        o[0]  = q[d].x * sc;
        o[64] = q[d].y * sc;
    }
}

// ------------------------- gather into packed head tensors -------------------------
__global__ void __launch_bounds__(256) k_gather(){
    __shared__ float tile[64][129];
    __shared__ int sidx[64];
    int tb = blockIdx.y;
    int cc = blockIdx.x;
    int pp0 = cc * 64;
    int f = pp0 / NN2, n0 = pp0 % NN2;
    int tid = threadIdx.x;
    if (tid < 64) sidx[tid] = g_idx[pp0 + tid];
    __syncthreads();
    long fb = (long)tb * POSN * 128;
    for (int i = tid; i < 64*128; i += 256){
        int ppl = i >> 7, val = i & 127;
        tile[ppl][val] = g_freq[fb + (long)sidx[ppl]*128 + val];
    }
    __syncthreads();
    long pb = (long)tb * NHEAD * 32 * NN2;
    for (int i = tid; i < 64*128; i += 256){
        int val = i >> 6, ppl = i & 63;
        int h = val >> 4, ci = val & 15;
        int j = ci*2 + f;
        g_pack[pb + (long)(h*32 + j)*NN2 + n0 + ppl] = tile[ppl][val];
    }
}

// ------------------------- Gram + norms (split-N with atomics) -------------------------
__global__ void __launch_bounds__(256) k_gram(){
    __shared__ float qS[32][130], kS[32][130];
    int bh = blockIdx.x;
    long qb = (long)bh * 32 * NN2;
    long kb = ((long)(NB*NHEAD) + bh) * 32 * NN2;
    int tid = threadIdx.x;
    int i2 = tid >> 4, j2 = tid & 15;
    float a00 = 0.f, a01 = 0.f, a10 = 0.f, a11 = 0.f, nacc = 0.f;
    for (int tile = blockIdx.y; tile < 129; tile += gridDim.y){
        int nc = tile * 128;
        __syncthreads();
        for (int i = tid; i < 32*128; i += 256){
            int r = i >> 7, n = i & 127;
            qS[r][n] = g_pack[qb + (long)r*NN2 + nc + n];
            kS[r][n] = g_pack[kb + (long)r*NN2 + nc + n];
        }
        __syncthreads();
#pragma unroll 4
        for (int n = 0; n < 128; n++){
            float q0 = qS[i2*2][n], q1 = qS[i2*2+1][n];
            float k0 = kS[j2*2][n], k1 = kS[j2*2+1][n];
            a00 += q0*k0; a01 += q0*k1; a10 += q1*k0; a11 += q1*k1;
        }
        if (tid < 64){
            const float* s = (tid < 32) ? &qS[tid][0] : &kS[tid-32][0];
            float acc = 0.f;
#pragma unroll 4
            for (int n = 0; n < 128; n++){ float v = s[n]; acc += v*v; }
            nacc += acc;
        }
    }
    float* G = g_gram + bh * 1024;
    int i = i2*2, j = j2*2;
    atomicAdd(&G[i*32 + j],       a00);
    atomicAdd(&G[i*32 + j + 1],   a01);
    atomicAdd(&G[(i+1)*32 + j],   a10);
    atomicAdd(&G[(i+1)*32 + j+1], a11);
    if (tid < 64) atomicAdd(&g_nrm[bh*64 + tid], nacc);
}

// ------------------------- softmax1 with folded l2norm + temperature -------------------------
__global__ void k_attn(const float* __restrict__ temp){
    int bh = blockIdx.x; int h = bh & 7;
    int i = threadIdx.y, j = threadIdx.x;
    float nq = sqrtf(g_nrm[bh*64 + i]);
    float nk = sqrtf(g_nrm[bh*64 + 32 + j]);
    float sc = temp[h] / (fmaxf(nq, 1e-12f) * fmaxf(nk, 1e-12f));
    float e = expf(g_gram[bh*1024 + i*32 + j] * sc);
    float s = e;
    #pragma unroll
    for (int d = 16; d; d >>= 1) s += __shfl_xor_sync(0xffffffffu, s, d);
    g_attn[bh*1024 + i*32 + j] = e / (s + 1.f);
}

// ------------------------- O = attn * V -------------------------
__global__ void __launch_bounds__(128) k_av(){
    __shared__ float vS[32][129];
    __shared__ float aS[32][32];
    int bh = blockIdx.y;
    int n0 = blockIdx.x * 128;
    long vb = ((long)(2*NB*NHEAD) + bh) * 32 * NN2;
    int tid = threadIdx.x;
    for (int i = tid; i < 1024; i += 128) aS[i >> 5][i & 31] = g_attn[bh*1024 + i];
    for (int i = tid; i < 32*128; i += 128){
        int r = i >> 7, n = i & 127;
        vS[r][n] = g_pack[vb + (long)r*NN2 + n0 + n];
    }
    __syncthreads();
    long ob = (long)bh * 32 * NN2;
    for (int i = 0; i < 32; i++){
        float a = 0.f;
        #pragma unroll 8
        for (int j = 0; j < 32; j++) a += aS[i][j] * vS[j][tid];
        g_opack[ob + (long)i*NN2 + n0 + tid] = a;
    }
}

// ------------------------- scatter back to freq layout -------------------------
__global__ void __launch_bounds__(256) k_scatter(){
    __shared__ float tile[128][65];
    __shared__ int sidx[64];
    int b = blockIdx.y, cc = blockIdx.x;
    int pp0 = cc * 64;
    int f = pp0 / NN2, n0 = pp0 % NN2;
    int tid = threadIdx.x;
    if (tid < 64) sidx[tid] = g_idx[pp0 + tid];
    __syncthreads();
    long pb = (long)b * NHEAD * 32 * NN2;
    for (int i = tid; i < 128*64; i += 256){
        int ppl = i & 63, val = i >> 6;
        int h = val >> 4, ci = val & 15;
        tile[val][ppl] = g_opack[pb + (long)(h*32 + ci*2 + f)*NN2 + n0 + ppl];
    }
    __syncthreads();
    long ob = (long)b * POSN * 128;
    for (int i = tid; i < 128*64; i += 256){
        int val = i & 127, ppl = i >> 7;
        g_ofreq[ob + (long)sidx[ppl]*128 + val] = tile[val][ppl];
    }
}

// ------------------------- inverse column FFT (along ky), 16x16 -------------------------
__global__ void __launch_bounds__(256) k_invcol(){
    __shared__ float2 zbuf[4096];
    __shared__ float2 tw[256];
    int tid = threadIdx.x;
    int gy = blockIdx.y; int b = gy / LL, kx = gy - b*LL;
    int cb = blockIdx.x * 16;
    build_tw256(tw, 1.f, tid);
    int bc = tid >> 4, ch = tid & 15;
    const float* src = g_ofreq + (long)b*POSN*128 + (long)kx*128 + cb + ch;
    float2 r[16];
#pragma unroll
    for (int a = 0; a < 16; a++){
        const float* p = src + (long)(a*16 + bc)*LL*128;
        r[a] = make_float2(p[0], p[64]);
    }
    __syncthreads();
    fft16r(r, 1.f);
#pragma unroll
    for (int c = 0; c < 16; c++) zbuf[(ch*16 + c)*16 + bc] = cmul(r[c], tw[bc*c]);
    __syncthreads();
    int c2 = tid >> 4, ch2 = tid & 15;
    float2 q[16];
#pragma unroll
    for (int b2 = 0; b2 < 16; b2++) q[b2] = zbuf[(ch2*16 + c2)*16 + b2];
    fft16r(q, 1.f);
    long ob = ((long)b*256*LL + kx) * 64 + cb + ch2;
#pragma unroll
    for (int d = 0; d < 16; d++){
        int yo = c2 + 16*d;
        g_backT[ob + (long)yo*LL*64] = q[d];
    }
}

// ------------------------- inverse row rfft (along x), channel-paired, 16x16 -------------------------
__global__ void __launch_bounds__(256) k_invrow(){
    __shared__ float2 zbuf[16*257];
    __shared__ float2 tw[256];
    int tid = threadIdx.x;
    int by = blockIdx.y; int b = by >> 8, y = by & 255;
    int cb = blockIdx.x * 32;
    build_tw256(tw, 1.f, tid);
    long ib = ((long)b*256 + y) * LL * 64 + cb;
    for (int i = tid; i < 16*129; i += 256){
        int k = i >> 4, p = i & 15;
        float4 v = *(const float4*)(g_backT + ib + (long)k*64 + 2*p);
        float2 A = make_float2(v.x, v.y), Bv = make_float2(v.z, v.w);
        if (k == 0 || k == 128){ A.y = 0.f; Bv.y = 0.f; }
        zbuf[p*257 + k] = make_float2(A.x - Bv.y, A.y + Bv.x);
        if (k >= 1 && k <= 127)
            zbuf[p*257 + 256 - k] = make_float2(A.x + Bv.y, Bv.x - A.y);
    }
    __syncthreads();
    int f = tid >> 4, bc = tid & 15;
    float2 r[16];
#pragma unroll
    for (int a = 0; a < 16; a++) r[a] = zbuf[f*257 + a*16 + bc];
    __syncthreads();                 // done reading stride-257 region
    fft16r(r, 1.f);
#pragma unroll
    for (int c = 0; c < 16; c++) zbuf[(f*16 + c)*16 + bc] = cmul(r[c], tw[bc*c]);
    __syncthreads();
    int c2 = tid & 15;
    float2 q[16];
#pragma unroll
    for (int b2 = 0; b2 < 16; b2++) q[b2] = zbuf[(f*16 + c2)*16 + b2];
    fft16r(q, 1.f);
    const float sc = 1.f/256.f;
    float* dre = g_spat + (long)(b*CIN + cb + 2*f) * PLANE + y*256;
    float* dim = dre + PLANE;
#pragma unroll
    for (int d = 0; d < 16; d++){
        int x = c2 + 16*d;
        dre[x] = q[d].x * sc;
        dim[x] = q[d].y * sc;
    }
}

// ------------------------- launch -------------------------
extern "C" void kernel_launch(void* const* d_in, const int* in_sizes, int n_in,
                              void* d_out, int out_size) {
    const float* x      = (const float*)d_in[0];
    const float* w_qkv  = (const float*)d_in[1];
    const float* w_dw   = (const float*)d_in[2];
    const float* w_proj = (const float*)d_in[3];
    const float* temp   = (const float*)d_in[4];
    float* out = (float*)d_out;

    k_zero<<<129, 256>>>();                      // 1
    k_hist<<<129, 256>>>();                      // 2
    k_scan<<<1, 256>>>();                        // 3
    k_convqkv<<<dim3(2048, 3), 256>>>(x, w_qkv); // 4 <- ncu capture slot
    k_fill<<<64, 256>>>();                       // 5 (before k_gather; dependency safe)

    k_dwconv<<<dim3(16, NB * COUT3), 256>>>(w_dw);

    k_rowfft<<<dim3(6, NB * 256), 256>>>();
    k_colfft<<<dim3(4, 12 * LL), 256>>>();

    k_gather<<<dim3(516, 12), 256>>>();
    k_gram<<<dim3(32, 16), 256>>>();
    k_attn<<<32, dim3(32, 32)>>>(temp);
    k_av<<<dim3(129, 32), 128>>>();
    k_scatter<<<dim3(516, NB), 256>>>();

    k_invcol<<<dim3(4, NB * LL), 256>>>();
    k_invrow<<<dim3(2, NB * 256), 256>>>();

    k_convproj<<<dim3(2048, 1), 256>>>(w_proj, out);
}

// round 13
// speedup vs baseline: 1.0108x; 1.0108x over previous
#include <cuda_runtime.h>
#include <cstdint>

#define NB 4
#define CIN 64
#define COUT3 192
#define LL 129
#define POSN 33024
#define NN2 16512
#define NHEAD 8
#define NBINS 16257
#define PLANE 65536

// ------------------------- device scratch (no allocation) -------------------------
__device__ float  g_qkv [NB*COUT3*PLANE];
__device__ float  g_qkv2[NB*COUT3*PLANE];
__device__ float2 g_rowA[(long)12*256*LL*64];     // [tb][y][k][64ch] complex
__device__ float  g_freq[(long)12*POSN*128];      // [tb][pos][re64|im64]
__device__ float  g_pack[(long)12*NHEAD*32*NN2];  // [tb][h][j][n]
__device__ float  g_opack[(long)NB*NHEAD*32*NN2];
__device__ float  g_ofreq[(long)NB*POSN*128];
__device__ float2 g_backT[(long)NB*256*LL*64];    // [b][y][k][64ch] complex
__device__ float  g_spat[(long)NB*CIN*PLANE];
__device__ float  g_gram[NB*NHEAD*32*32];
__device__ float  g_nrm [NB*NHEAD*64];
__device__ float  g_attn[NB*NHEAD*32*32];
__device__ int    g_hist[NBINS];
__device__ int    g_off [NBINS];
__device__ int    g_idx [POSN];

// ------------------------- helpers -------------------------
__device__ __forceinline__ float2 cmul(float2 a, float2 b){
    return make_float2(a.x*b.x - a.y*b.y, a.x*b.y + a.y*b.x);
}

// packed f32x2 helpers (base sm_100+ PTX; NOT an "a"-gated feature)
__device__ __forceinline__ unsigned long long pack2(float lo, float hi){
    unsigned long long d;
    asm("mov.b64 %0, {%1, %2};" : "=l"(d) : "f"(lo), "f"(hi));
    return d;
}
__device__ __forceinline__ unsigned long long pack2b(float v){
    unsigned long long d;
    asm("mov.b64 %0, {%1, %1};" : "=l"(d) : "f"(v));
    return d;
}
__device__ __forceinline__ void ffma2(unsigned long long& d, unsigned long long a, unsigned long long b){
    asm("fma.rn.f32x2 %0, %1, %2, %0;" : "+l"(d) : "l"(a), "l"(b));
}
__device__ __forceinline__ float2 unpack2(unsigned long long v){
    float2 r;
    asm("mov.b64 {%0, %1}, %2;" : "=f"(r.x), "=f"(r.y) : "l"(v));
    return r;
}

// 16-point radix-2 DIT FFT fully in registers. sgn=-1 forward, +1 inverse.
__device__ __forceinline__ void fft16r(float2* r, float sgn){
    float2 t;
#define SWP(a,b) { t=r[a]; r[a]=r[b]; r[b]=t; }
    SWP(1,8) SWP(2,4) SWP(3,12) SWP(5,10) SWP(7,14) SWP(11,13)
#undef SWP
    const float C[8] = {1.f, 0.92387953251f, 0.70710678119f, 0.38268343236f,
                        0.f, -0.38268343236f, -0.70710678119f, -0.92387953251f};
    const float S[8] = {0.f, 0.38268343236f, 0.70710678119f, 0.92387953251f,
                        1.f, 0.92387953251f, 0.70710678119f, 0.38268343236f};
#pragma unroll
    for (int s = 0; s < 4; s++){
        int half = 1 << s;
#pragma unroll
        for (int k = 0; k < 8; k++){
            int j = k & (half-1);
            int base = ((k>>s)<<(s+1)) + j;
            int m = j << (3-s);
            float2 w = make_float2(C[m], sgn*S[m]);
            float2 a = r[base];
            float2 b = cmul(r[base+half], w);
            r[base]      = make_float2(a.x+b.x, a.y+b.y);
            r[base+half] = make_float2(a.x-b.x, a.y-b.y);
        }
    }
}

__device__ __forceinline__ void build_tw256(float2* tw, float sgn, int tid){
    float ang = sgn * 6.283185307179586f * (float)tid / 256.0f;
    float s, c; sincosf(ang, &s, &c);
    tw[tid] = make_float2(c, s);
}

// ------------------------- permutation -------------------------
__global__ void k_zero(){
    int i = blockIdx.x * 256 + threadIdx.x;
    if (i < NBINS) g_hist[i] = 0;
    if (i < 32*1024) g_gram[i] = 0.f;
    if (i < 32*64) g_nrm[i] = 0.f;
}
__global__ void k_hist(){
    int j = blockIdx.x * 256 + threadIdx.x;
    if (j < POSN){
        int r = j / LL, l = j % LL;
        int m = (r < 128) ? r : 255 - r;
        atomicAdd(&g_hist[m * l], 1);
    }
}
__global__ void k_scan(){
    __shared__ int part[256];
    int tid = threadIdx.x;
    int s = 0;
    for (int i = 0; i < 64; i++){
        int K = tid * 64 + i;
        if (K < NBINS) s += g_hist[K];
    }
    part[tid] = s;
    __syncthreads();
    if (tid == 0){
        int run = 0;
        for (int i = 0; i < 256; i++){ int t = part[i]; part[i] = run; run += t; }
    }
    __syncthreads();
    int run = part[tid];
    for (int i = 0; i < 64; i++){
        int K = tid * 64 + i;
        if (K < NBINS){ g_off[K] = run; run += g_hist[K]; }
    }
}
__global__ void k_fill(){
    int K = blockIdx.x * 256 + threadIdx.x;
    if (K >= NBINS) return;
    int o = g_off[K];
    if (K == 0){
        for (int l = 0; l <= 128; l++) g_idx[o++] = l;
        for (int r = 1; r <= 254; r++) g_idx[o++] = r * LL;
        for (int l = 0; l <= 128; l++) g_idx[o++] = 255 * LL + l;
    } else {
        for (int v = 1; v <= 127; v++)
            if (K % v == 0){ int l = K / v; if (l <= 128) g_idx[o++] = v * LL + l; }
        for (int v = 127; v >= 1; v--)
            if (K % v == 0){ int l = K / v; if (l <= 128) g_idx[o++] = (255 - v) * LL + l; }
    }
}

// ------------------------- 1x1 conv (f32x2, double-buffered software pipeline) -------------------------
template<int OC>
__device__ __forceinline__ void conv_body(const float* __restrict__ x,
                                          const float* __restrict__ w,
                                          float* __restrict__ out){
    __shared__ float xS[2][8][128];
    __shared__ float wS[2][8][64];
    int p0 = blockIdx.x * 128;
    int og = blockIdx.y * 64;
    int b = p0 / PLANE; int pp = p0 % PLANE;
    int tid = threadIdx.x;
    int tx = tid & 15, ty = tid >> 4;
    unsigned long long acc[4][4];
    #pragma unroll
    for (int i = 0; i < 4; i++)
        #pragma unroll
        for (int j = 0; j < 4; j++) acc[i][j] = 0ull;

    float xr[4], wr[2];
    // prologue: stage chunk 0 into buffer 0
    #pragma unroll
    for (int k = 0; k < 4; k++){
        int i = tid + k * 256;
        xr[k] = x[(long)(b * CIN + (i >> 7)) * PLANE + pp + (i & 127)];
    }
    #pragma unroll
    for (int k = 0; k < 2; k++){
        int i = tid + k * 256;
        wr[k] = w[(og + (i & 63)) * CIN + (i >> 6)];
    }
    #pragma unroll
    for (int k = 0; k < 4; k++){
        int i = tid + k * 256;
        xS[0][i >> 7][i & 127] = xr[k];
    }
    #pragma unroll
    for (int k = 0; k < 2; k++){
        int i = tid + k * 256;
        wS[0][i >> 6][i & 63] = wr[k];
    }
    __syncthreads();

    int buf = 0;
    for (int c0 = 0; c0 < 64; c0 += 8){
        bool more = (c0 + 8 < 64);
        if (more){
            #pragma unroll
            for (int k = 0; k < 4; k++){
                int i = tid + k * 256;
                xr[k] = x[(long)(b * CIN + c0 + 8 + (i >> 7)) * PLANE + pp + (i & 127)];
            }
            #pragma unroll
            for (int k = 0; k < 2; k++){
                int i = tid + k * 256;
                wr[k] = w[(og + (i & 63)) * CIN + c0 + 8 + (i >> 6)];
            }
        }
        // compute current buffer (round-11 proven inner loop)
        #pragma unroll
        for (int cc = 0; cc < 8; cc++){
            unsigned long long wr2[4], xr2[4];
            #pragma unroll
            for (int i = 0; i < 4; i++) wr2[i] = pack2b(wS[buf][cc][ty * 4 + i]);
            #pragma unroll
            for (int j = 0; j < 4; j++){
                float2 v = *(const float2*)&xS[buf][cc][tx * 8 + 2 * j];
                xr2[j] = pack2(v.x, v.y);
            }
            #pragma unroll
            for (int i = 0; i < 4; i++)
                #pragma unroll
                for (int j = 0; j < 4; j++) ffma2(acc[i][j], wr2[i], xr2[j]);
        }
        if (more){
            int nb = buf ^ 1;
            #pragma unroll
            for (int k = 0; k < 4; k++){
                int i = tid + k * 256;
                xS[nb][i >> 7][i & 127] = xr[k];
            }
            #pragma unroll
            for (int k = 0; k < 2; k++){
                int i = tid + k * 256;
                wS[nb][i >> 6][i & 63] = wr[k];
            }
            __syncthreads();
            buf = nb;
        }
    }
    #pragma unroll
    for (int i = 0; i < 4; i++){
        int o = og + ty * 4 + i;
        float* dst = out + (long)(b * OC + o) * PLANE + pp + tx * 8;
        #pragma unroll
        for (int j = 0; j < 4; j++) *(float2*)(dst + 2 * j) = unpack2(acc[i][j]);
    }
}
__global__ void __launch_bounds__(256) k_convqkv(const float* __restrict__ x, const float* __restrict__ w){
    conv_body<COUT3>(x, w, g_qkv);
}
__global__ void __launch_bounds__(256) k_convproj(const float* __restrict__ w, float* __restrict__ out){
    conv_body<CIN>(g_spat, w, out);
}

// ------------------------- 3x3 depthwise conv -------------------------
__global__ void __launch_bounds__(256) k_dwconv(const float* __restrict__ wdw){
    __shared__ float sm[18][258];
    int bc = blockIdx.y;
    int ch = bc % COUT3;
    int y0 = blockIdx.x * 16;
    int tid = threadIdx.x;
    const float* src = g_qkv + (long)bc * PLANE;
    for (int i = tid; i < 18 * 258; i += 256){
        int r = i / 258, cc = i % 258;
        int gy = y0 + r - 1, gx = cc - 1;
        float v = 0.f;
        if ((unsigned)gy < 256u && (unsigned)gx < 256u) v = src[gy * 256 + gx];
        sm[r][cc] = v;
    }
    float w[9];
    #pragma unroll
    for (int i = 0; i < 9; i++) w[i] = wdw[ch * 9 + i];
    __syncthreads();
    int x = tid;
    float* dst = g_qkv2 + (long)bc * PLANE;
    for (int yy = 0; yy < 16; yy++){
        float a = 0.f;
        #pragma unroll
        for (int dy = 0; dy < 3; dy++)
            #pragma unroll
            for (int dx = 0; dx < 3; dx++)
                a += w[dy * 3 + dx] * sm[yy + dy][x + dx];
        dst[(y0 + yy) * 256 + x] = a;
    }
}

// ------------------------- row rfft (along x), channel-paired, 16x16 -------------------------
__global__ void __launch_bounds__(256) k_rowfft(){
    __shared__ float2 zbuf[16*257];
    __shared__ float2 tw[256];
    int tid = threadIdx.x;
    int by = blockIdx.y; int b = by >> 8, y = by & 255;
    int ch0 = blockIdx.x * 32;
    build_tw256(tw, -1.f, tid);
    int f = tid >> 4, bc = tid & 15;
    const float* re = g_qkv2 + (long)(b * COUT3 + ch0 + 2*f) * PLANE + y * 256;
    const float* im = re + PLANE;
    float2 r[16];
#pragma unroll
    for (int a = 0; a < 16; a++){ int x = a*16 + bc; r[a] = make_float2(re[x], im[x]); }
    __syncthreads();                 // tw ready
    fft16r(r, -1.f);
#pragma unroll
    for (int c = 0; c < 16; c++) zbuf[(f*16 + c)*16 + bc] = cmul(r[c], tw[bc*c]);
    __syncthreads();
    int c2 = tid & 15;
    float2 q[16];
#pragma unroll
    for (int b2 = 0; b2 < 16; b2++) q[b2] = zbuf[(f*16 + c2)*16 + b2];
    __syncthreads();                 // before re-using zbuf with stride 257
    fft16r(q, -1.f);
#pragma unroll
    for (int d = 0; d < 16; d++) zbuf[f*257 + c2 + 16*d] = q[d];
    __syncthreads();
    int t = ch0 >> 6, cb = ch0 & 63;
    long base = (((long)(t*NB + b) * 256 + y) * LL) * 64 + cb;
    for (int i = tid; i < 16*129; i += 256){
        int k = i >> 4, p = i & 15;
        float2 Zk = zbuf[p*257 + k];
        float2 Zm = zbuf[p*257 + ((256 - k) & 255)];
        float4 v = make_float4(0.5f*(Zk.x + Zm.x), 0.5f*(Zk.y - Zm.y),
                               0.5f*(Zk.y + Zm.y), 0.5f*(Zm.x - Zk.x));
        *(float4*)(g_rowA + base + (long)k*64 + 2*p) = v;
    }
}

// ------------------------- column FFT (along y), 16x16 -------------------------
__global__ void __launch_bounds__(256) k_colfft(){
    __shared__ float2 zbuf[4096];
    __shared__ float2 tw[256];
    int tid = threadIdx.x;
    int gy = blockIdx.y; int tb = gy / LL, kx = gy - tb*LL;
    int cb = blockIdx.x * 16;
    build_tw256(tw, -1.f, tid);
    int bc = tid >> 4, ch = tid & 15;
    const float2* src = g_rowA + ((long)tb*256*LL + kx) * 64 + cb + ch;
    float2 r[16];
#pragma unroll
    for (int a = 0; a < 16; a++) r[a] = src[(long)(a*16 + bc) * LL * 64];
    __syncthreads();
    fft16r(r, -1.f);
#pragma unroll
    for (int c = 0; c < 16; c++) zbuf[(ch*16 + c)*16 + bc] = cmul(r[c], tw[bc*c]);
    __syncthreads();
    int c2 = tid >> 4, ch2 = tid & 15;
    float2 q[16];
#pragma unroll
    for (int b2 = 0; b2 < 16; b2++) q[b2] = zbuf[(ch2*16 + c2)*16 + b2];
    fft16r(q, -1.f);
    const float sc = 1.f/256.f;
    long ob = (long)tb*POSN*128 + (long)kx*128 + cb + ch2;
#pragma unroll
    for (int d = 0; d < 16; d++){
        int ky = c2 + 16*d;
        float* o = g_freq + ob + (long)ky*LL*128;
        o[0]  = q[d].x * sc;
        o[64] = q[d].y * sc;
    }
}

// ------------------------- gather into packed head tensors -------------------------
__global__ void __launch_bounds__(256) k_gather(){
    __shared__ float tile[64][129];
    __shared__ int sidx[64];
    int tb = blockIdx.y;
    int cc = blockIdx.x;
    int pp0 = cc * 64;
    int f = pp0 / NN2, n0 = pp0 % NN2;
    int tid = threadIdx.x;
    if (tid < 64) sidx[tid] = g_idx[pp0 + tid];
    __syncthreads();
    long fb = (long)tb * POSN * 128;
    for (int i = tid; i < 64*128; i += 256){
        int ppl = i >> 7, val = i & 127;
        tile[ppl][val] = g_freq[fb + (long)sidx[ppl]*128 + val];
    }
    __syncthreads();
    long pb = (long)tb * NHEAD * 32 * NN2;
    for (int i = tid; i < 64*128; i += 256){
        int val = i >> 6, ppl = i & 63;
        int h = val >> 4, ci = val & 15;
        int j = ci*2 + f;
        g_pack[pb + (long)(h*32 + j)*NN2 + n0 + ppl] = tile[ppl][val];
    }
}

// ------------------------- Gram + norms (split-N with atomics) -------------------------
__global__ void __launch_bounds__(256) k_gram(){
    __shared__ float qS[32][130], kS[32][130];
    int bh = blockIdx.x;
    long qb = (long)bh * 32 * NN2;
    long kb = ((long)(NB*NHEAD) + bh) * 32 * NN2;
    int tid = threadIdx.x;
    int i2 = tid >> 4, j2 = tid & 15;
    float a00 = 0.f, a01 = 0.f, a10 = 0.f, a11 = 0.f, nacc = 0.f;
    for (int tile = blockIdx.y; tile < 129; tile += gridDim.y){
        int nc = tile * 128;
        __syncthreads();
        for (int i = tid; i < 32*128; i += 256){
            int r = i >> 7, n = i & 127;
            qS[r][n] = g_pack[qb + (long)r*NN2 + nc + n];
            kS[r][n] = g_pack[kb + (long)r*NN2 + nc + n];
        }
        __syncthreads();
#pragma unroll 4
        for (int n = 0; n < 128; n++){
            float q0 = qS[i2*2][n], q1 = qS[i2*2+1][n];
            float k0 = kS[j2*2][n], k1 = kS[j2*2+1][n];
            a00 += q0*k0; a01 += q0*k1; a10 += q1*k0; a11 += q1*k1;
        }
        if (tid < 64){
            const float* s = (tid < 32) ? &qS[tid][0] : &kS[tid-32][0];
            float acc = 0.f;
#pragma unroll 4
            for (int n = 0; n < 128; n++){ float v = s[n]; acc += v*v; }
            nacc += acc;
        }
    }
    float* G = g_gram + bh * 1024;
    int i = i2*2, j = j2*2;
    atomicAdd(&G[i*32 + j],       a00);
    atomicAdd(&G[i*32 + j + 1],   a01);
    atomicAdd(&G[(i+1)*32 + j],   a10);
    atomicAdd(&G[(i+1)*32 + j+1], a11);
    if (tid < 64) atomicAdd(&g_nrm[bh*64 + tid], nacc);
}

// ------------------------- softmax1 with folded l2norm + temperature -------------------------
__global__ void k_attn(const float* __restrict__ temp){
    int bh = blockIdx.x; int h = bh & 7;
    int i = threadIdx.y, j = threadIdx.x;
    float nq = sqrtf(g_nrm[bh*64 + i]);
    float nk = sqrtf(g_nrm[bh*64 + 32 + j]);
    float sc = temp[h] / (fmaxf(nq, 1e-12f) * fmaxf(nk, 1e-12f));
    float e = expf(g_gram[bh*1024 + i*32 + j] * sc);
    float s = e;
    #pragma unroll
    for (int d = 16; d; d >>= 1) s += __shfl_xor_sync(0xffffffffu, s, d);
    g_attn[bh*1024 + i*32 + j] = e / (s + 1.f);
}

// ------------------------- O = attn * V -------------------------
__global__ void __launch_bounds__(128) k_av(){
    __shared__ float vS[32][129];
    __shared__ float aS[32][32];
    int bh = blockIdx.y;
    int n0 = blockIdx.x * 128;
    long vb = ((long)(2*NB*NHEAD) + bh) * 32 * NN2;
    int tid = threadIdx.x;
    for (int i = tid; i < 1024; i += 128) aS[i >> 5][i & 31] = g_attn[bh*1024 + i];
    for (int i = tid; i < 32*128; i += 128){
        int r = i >> 7, n = i & 127;
        vS[r][n] = g_pack[vb + (long)r*NN2 + n0 + n];
    }
    __syncthreads();
    long ob = (long)bh * 32 * NN2;
    for (int i = 0; i < 32; i++){
        float a = 0.f;
        #pragma unroll 8
        for (int j = 0; j < 32; j++) a += aS[i][j] * vS[j][tid];
        g_opack[ob + (long)i*NN2 + n0 + tid] = a;
    }
}

// ------------------------- scatter back to freq layout -------------------------
__global__ void __launch_bounds__(256) k_scatter(){
    __shared__ float tile[128][65];
    __shared__ int sidx[64];
    int b = blockIdx.y, cc = blockIdx.x;
    int pp0 = cc * 64;
    int f = pp0 / NN2, n0 = pp0 % NN2;
    int tid = threadIdx.x;
    if (tid < 64) sidx[tid] = g_idx[pp0 + tid];
    __syncthreads();
    long pb = (long)b * NHEAD * 32 * NN2;
    for (int i = tid; i < 128*64; i += 256){
        int ppl = i & 63, val = i >> 6;
        int h = val >> 4, ci = val & 15;
        tile[val][ppl] = g_opack[pb + (long)(h*32 + ci*2 + f)*NN2 + n0 + ppl];
    }
    __syncthreads();
    long ob = (long)b * POSN * 128;
    for (int i = tid; i < 128*64; i += 256){
        int val = i & 127, ppl = i >> 7;
        g_ofreq[ob + (long)sidx[ppl]*128 + val] = tile[val][ppl];
    }
}

// ------------------------- inverse column FFT (along ky), 16x16 -------------------------
__global__ void __launch_bounds__(256) k_invcol(){
    __shared__ float2 zbuf[4096];
    __shared__ float2 tw[256];
    int tid = threadIdx.x;
    int gy = blockIdx.y; int b = gy / LL, kx = gy - b*LL;
    int cb = blockIdx.x * 16;
    build_tw256(tw, 1.f, tid);
    int bc = tid >> 4, ch = tid & 15;
    const float* src = g_ofreq + (long)b*POSN*128 + (long)kx*128 + cb + ch;
    float2 r[16];
#pragma unroll
    for (int a = 0; a < 16; a++){
        const float* p = src + (long)(a*16 + bc)*LL*128;
        r[a] = make_float2(p[0], p[64]);
    }
    __syncthreads();
    fft16r(r, 1.f);
#pragma unroll
    for (int c = 0; c < 16; c++) zbuf[(ch*16 + c)*16 + bc] = cmul(r[c], tw[bc*c]);
    __syncthreads();
    int c2 = tid >> 4, ch2 = tid & 15;
    float2 q[16];
#pragma unroll
    for (int b2 = 0; b2 < 16; b2++) q[b2] = zbuf[(ch2*16 + c2)*16 + b2];
    fft16r(q, 1.f);
    long ob = ((long)b*256*LL + kx) * 64 + cb + ch2;
#pragma unroll
    for (int d = 0; d < 16; d++){
        int yo = c2 + 16*d;
        g_backT[ob + (long)yo*LL*64] = q[d];
    }
}

// ------------------------- inverse row rfft (along x), channel-paired, 16x16 -------------------------
__global__ void __launch_bounds__(256) k_invrow(){
    __shared__ float2 zbuf[16*257];
    __shared__ float2 tw[256];
    int tid = threadIdx.x;
    int by = blockIdx.y; int b = by >> 8, y = by & 255;
    int cb = blockIdx.x * 32;
    build_tw256(tw, 1.f, tid);
    long ib = ((long)b*256 + y) * LL * 64 + cb;
    for (int i = tid; i < 16*129; i += 256){
        int k = i >> 4, p = i & 15;
        float4 v = *(const float4*)(g_backT + ib + (long)k*64 + 2*p);
        float2 A = make_float2(v.x, v.y), Bv = make_float2(v.z, v.w);
        if (k == 0 || k == 128){ A.y = 0.f; Bv.y = 0.f; }
        zbuf[p*257 + k] = make_float2(A.x - Bv.y, A.y + Bv.x);
        if (k >= 1 && k <= 127)
            zbuf[p*257 + 256 - k] = make_float2(A.x + Bv.y, Bv.x - A.y);
    }
    __syncthreads();
    int f = tid >> 4, bc = tid & 15;
    float2 r[16];
#pragma unroll
    for (int a = 0; a < 16; a++) r[a] = zbuf[f*257 + a*16 + bc];
    __syncthreads();                 // done reading stride-257 region
    fft16r(r, 1.f);
#pragma unroll
    for (int c = 0; c < 16; c++) zbuf[(f*16 + c)*16 + bc] = cmul(r[c], tw[bc*c]);
    __syncthreads();
    int c2 = tid & 15;
    float2 q[16];
#pragma unroll
    for (int b2 = 0; b2 < 16; b2++) q[b2] = zbuf[(f*16 + c2)*16 + b2];
    fft16r(q, 1.f);
    const float sc = 1.f/256.f;
    float* dre = g_spat + (long)(b*CIN + cb + 2*f) * PLANE + y*256;
    float* dim = dre + PLANE;
#pragma unroll
    for (int d = 0; d < 16; d++){
        int x = c2 + 16*d;
        dre[x] = q[d].x * sc;
        dim[x] = q[d].y * sc;
    }
}

// ------------------------- launch -------------------------
extern "C" void kernel_launch(void* const* d_in, const int* in_sizes, int n_in,
                              void* d_out, int out_size) {
    const float* x      = (const float*)d_in[0];
    const float* w_qkv  = (const float*)d_in[1];
    const float* w_dw   = (const float*)d_in[2];
    const float* w_proj = (const float*)d_in[3];
    const float* temp   = (const float*)d_in[4];
    float* out = (float*)d_out;

    k_zero<<<129, 256>>>();                      // 1
    k_hist<<<129, 256>>>();                      // 2
    k_scan<<<1, 256>>>();                        // 3
    k_convqkv<<<dim3(2048, 3), 256>>>(x, w_qkv); // 4 <- ncu capture slot
    k_fill<<<64, 256>>>();                       // 5 (before k_gather; dependency safe)

    k_dwconv<<<dim3(16, NB * COUT3), 256>>>(w_dw);

    k_rowfft<<<dim3(6, NB * 256), 256>>>();
    k_colfft<<<dim3(4, 12 * LL), 256>>>();

    k_gather<<<dim3(516, 12), 256>>>();
    k_gram<<<dim3(32, 16), 256>>>();
    k_attn<<<32, dim3(32, 32)>>>(temp);
    k_av<<<dim3(129, 32), 128>>>();
    k_scatter<<<dim3(516, NB), 256>>>();

    k_invcol<<<dim3(4, NB * LL), 256>>>();
    k_invrow<<<dim3(2, NB * 256), 256>>>();

    k_convproj<<<dim3(2048, 1), 256>>>(w_proj, out);
}

// round 14
// speedup vs baseline: 1.0995x; 1.0877x over previous
#include <cuda_runtime.h>
#include <cstdint>

#define NB 4
#define CIN 64
#define COUT3 192
#define LL 129
#define POSN 33024
#define NN2 16512
#define NHEAD 8
#define NBINS 16257
#define PLANE 65536

// ------------------------- device scratch (no allocation) -------------------------
__device__ float  g_qkv [NB*COUT3*PLANE];
__device__ float  g_qkv2[NB*COUT3*PLANE];
__device__ float2 g_rowA[(long)12*256*LL*64];     // [tb][y][k][64ch] complex
__device__ float  g_freq[(long)12*POSN*128];      // [tb][pos][re64|im64]
__device__ float  g_pack[(long)12*NHEAD*32*NN2];  // [tb][h][j][n]
__device__ float  g_opack[(long)NB*NHEAD*32*NN2];
__device__ float  g_ofreq[(long)NB*POSN*128];
__device__ float2 g_backT[(long)NB*256*LL*64];    // [b][y][k][64ch] complex
__device__ float  g_spat[(long)NB*CIN*PLANE];
__device__ float  g_gram[NB*NHEAD*32*32];
__device__ float  g_nrm [NB*NHEAD*64];
__device__ float  g_attn[NB*NHEAD*32*32];
__device__ int    g_hist[NBINS];
__device__ int    g_off [NBINS];
__device__ int    g_idx [POSN];

// ------------------------- helpers -------------------------
__device__ __forceinline__ float2 cmul(float2 a, float2 b){
    return make_float2(a.x*b.x - a.y*b.y, a.x*b.y + a.y*b.x);
}

// packed f32x2 helpers (base sm_100+ PTX; NOT an "a"-gated feature)
__device__ __forceinline__ unsigned long long pack2(float lo, float hi){
    unsigned long long d;
    asm("mov.b64 %0, {%1, %2};" : "=l"(d) : "f"(lo), "f"(hi));
    return d;
}
__device__ __forceinline__ unsigned long long pack2b(float v){
    unsigned long long d;
    asm("mov.b64 %0, {%1, %1};" : "=l"(d) : "f"(v));
    return d;
}
__device__ __forceinline__ void ffma2(unsigned long long& d, unsigned long long a, unsigned long long b){
    asm("fma.rn.f32x2 %0, %1, %2, %0;" : "+l"(d) : "l"(a), "l"(b));
}
__device__ __forceinline__ float2 unpack2(unsigned long long v){
    float2 r;
    asm("mov.b64 {%0, %1}, %2;" : "=f"(r.x), "=f"(r.y) : "l"(v));
    return r;
}

// 16-point radix-2 DIT FFT fully in registers. sgn=-1 forward, +1 inverse.
__device__ __forceinline__ void fft16r(float2* r, float sgn){
    float2 t;
#define SWP(a,b) { t=r[a]; r[a]=r[b]; r[b]=t; }
    SWP(1,8) SWP(2,4) SWP(3,12) SWP(5,10) SWP(7,14) SWP(11,13)
#undef SWP
    const float C[8] = {1.f, 0.92387953251f, 0.70710678119f, 0.38268343236f,
                        0.f, -0.38268343236f, -0.70710678119f, -0.92387953251f};
    const float S[8] = {0.f, 0.38268343236f, 0.70710678119f, 0.92387953251f,
                        1.f, 0.92387953251f, 0.70710678119f, 0.38268343236f};
#pragma unroll
    for (int s = 0; s < 4; s++){
        int half = 1 << s;
#pragma unroll
        for (int k = 0; k < 8; k++){
            int j = k & (half-1);
            int base = ((k>>s)<<(s+1)) + j;
            int m = j << (3-s);
            float2 w = make_float2(C[m], sgn*S[m]);
            float2 a = r[base];
            float2 b = cmul(r[base+half], w);
            r[base]      = make_float2(a.x+b.x, a.y+b.y);
            r[base+half] = make_float2(a.x-b.x, a.y-b.y);
        }
    }
}

__device__ __forceinline__ void build_tw256(float2* tw, float sgn, int tid){
    float ang = sgn * 6.283185307179586f * (float)tid / 256.0f;
    float s, c; sincosf(ang, &s, &c);
    tw[tid] = make_float2(c, s);
}

// ------------------------- permutation -------------------------
__global__ void k_zero(){
    int i = blockIdx.x * 256 + threadIdx.x;
    if (i < NBINS) g_hist[i] = 0;
    if (i < 32*1024) g_gram[i] = 0.f;
    if (i < 32*64) g_nrm[i] = 0.f;
}
__global__ void k_hist(){
    int j = blockIdx.x * 256 + threadIdx.x;
    if (j < POSN){
        int r = j / LL, l = j % LL;
        int m = (r < 128) ? r : 255 - r;
        atomicAdd(&g_hist[m * l], 1);
    }
}
__global__ void k_scan(){
    __shared__ int part[256];
    int tid = threadIdx.x;
    int s = 0;
    for (int i = 0; i < 64; i++){
        int K = tid * 64 + i;
        if (K < NBINS) s += g_hist[K];
    }
    part[tid] = s;
    __syncthreads();
    if (tid == 0){
        int run = 0;
        for (int i = 0; i < 256; i++){ int t = part[i]; part[i] = run; run += t; }
    }
    __syncthreads();
    int run = part[tid];
    for (int i = 0; i < 64; i++){
        int K = tid * 64 + i;
        if (K < NBINS){ g_off[K] = run; run += g_hist[K]; }
    }
}
__global__ void k_fill(){
    int K = blockIdx.x * 256 + threadIdx.x;
    if (K >= NBINS) return;
    int o = g_off[K];
    if (K == 0){
        for (int l = 0; l <= 128; l++) g_idx[o++] = l;
        for (int r = 1; r <= 254; r++) g_idx[o++] = r * LL;
        for (int l = 0; l <= 128; l++) g_idx[o++] = 255 * LL + l;
    } else {
        for (int v = 1; v <= 127; v++)
            if (K % v == 0){ int l = K / v; if (l <= 128) g_idx[o++] = v * LL + l; }
        for (int v = 127; v >= 1; v--)
            if (K % v == 0){ int l = K / v; if (l <= 128) g_idx[o++] = (255 - v) * LL + l; }
    }
}

// ------------------------- 1x1 conv (8oc x 8px per thread, f32x2, double-buffered) -------------------------
// Block: 64 oc x 256 px, 256 threads. ty = tid>>5 (oc octet, warp-uniform -> w reads broadcast),
// tx = tid&31 (px octet). acc[8][4] f32x2.
template<int OC>
__device__ __forceinline__ void conv_body(const float* __restrict__ x,
                                          const float* __restrict__ w,
                                          float* __restrict__ out){
    __shared__ float xS[2][8][256];
    __shared__ float wS[2][8][64];
    int p0 = blockIdx.x * 256;
    int og = blockIdx.y * 64;
    int b = p0 / PLANE; int pp = p0 % PLANE;
    int tid = threadIdx.x;
    int tx = tid & 31, ty = tid >> 5;
    unsigned long long acc[8][4];
    #pragma unroll
    for (int i = 0; i < 8; i++)
        #pragma unroll
        for (int j = 0; j < 4; j++) acc[i][j] = 0ull;

    float xr[8], wr[2];
    // prologue: stage chunk 0 into buffer 0
    #pragma unroll
    for (int k = 0; k < 8; k++){
        int i = tid + k * 256;
        xr[k] = x[(long)(b * CIN + (i >> 8)) * PLANE + pp + (i & 255)];
    }
    #pragma unroll
    for (int k = 0; k < 2; k++){
        int i = tid + k * 256;
        wr[k] = w[(og + (i & 63)) * CIN + (i >> 6)];
    }
    #pragma unroll
    for (int k = 0; k < 8; k++){
        int i = tid + k * 256;
        xS[0][i >> 8][i & 255] = xr[k];
    }
    #pragma unroll
    for (int k = 0; k < 2; k++){
        int i = tid + k * 256;
        wS[0][i >> 6][i & 63] = wr[k];
    }
    __syncthreads();

    int buf = 0;
    for (int c0 = 0; c0 < 64; c0 += 8){
        bool more = (c0 + 8 < 64);
        if (more){
            #pragma unroll
            for (int k = 0; k < 8; k++){
                int i = tid + k * 256;
                xr[k] = x[(long)(b * CIN + c0 + 8 + (i >> 8)) * PLANE + pp + (i & 255)];
            }
            #pragma unroll
            for (int k = 0; k < 2; k++){
                int i = tid + k * 256;
                wr[k] = w[(og + (i & 63)) * CIN + c0 + 8 + (i >> 6)];
            }
        }
        #pragma unroll
        for (int cc = 0; cc < 8; cc++){
            float4 wv0 = *(const float4*)&wS[buf][cc][ty * 8];      // warp-broadcast
            float4 wv1 = *(const float4*)&wS[buf][cc][ty * 8 + 4];
            unsigned long long wr2[8];
            wr2[0] = pack2b(wv0.x); wr2[1] = pack2b(wv0.y);
            wr2[2] = pack2b(wv0.z); wr2[3] = pack2b(wv0.w);
            wr2[4] = pack2b(wv1.x); wr2[5] = pack2b(wv1.y);
            wr2[6] = pack2b(wv1.z); wr2[7] = pack2b(wv1.w);
            float4 v0 = *(const float4*)&xS[buf][cc][tx * 8];
            float4 v1 = *(const float4*)&xS[buf][cc][tx * 8 + 4];
            unsigned long long xr2[4];
            xr2[0] = pack2(v0.x, v0.y); xr2[1] = pack2(v0.z, v0.w);
            xr2[2] = pack2(v1.x, v1.y); xr2[3] = pack2(v1.z, v1.w);
            #pragma unroll
            for (int i = 0; i < 8; i++)
                #pragma unroll
                for (int j = 0; j < 4; j++) ffma2(acc[i][j], wr2[i], xr2[j]);
        }
        if (more){
            int nb = buf ^ 1;
            #pragma unroll
            for (int k = 0; k < 8; k++){
                int i = tid + k * 256;
                xS[nb][i >> 8][i & 255] = xr[k];
            }
            #pragma unroll
            for (int k = 0; k < 2; k++){
                int i = tid + k * 256;
                wS[nb][i >> 6][i & 63] = wr[k];
            }
            __syncthreads();
            buf = nb;
        }
    }
    #pragma unroll
    for (int i = 0; i < 8; i++){
        int o = og + ty * 8 + i;
        float* dst = out + (long)(b * OC + o) * PLANE + pp + tx * 8;
        #pragma unroll
        for (int j = 0; j < 4; j++) *(float2*)(dst + 2 * j) = unpack2(acc[i][j]);
    }
}
__global__ void __launch_bounds__(256) k_convqkv(const float* __restrict__ x, const float* __restrict__ w){
    conv_body<COUT3>(x, w, g_qkv);
}
__global__ void __launch_bounds__(256) k_convproj(const float* __restrict__ w, float* __restrict__ out){
    conv_body<CIN>(g_spat, w, out);
}

// ------------------------- 3x3 depthwise conv -------------------------
__global__ void __launch_bounds__(256) k_dwconv(const float* __restrict__ wdw){
    __shared__ float sm[18][258];
    int bc = blockIdx.y;
    int ch = bc % COUT3;
    int y0 = blockIdx.x * 16;
    int tid = threadIdx.x;
    const float* src = g_qkv + (long)bc * PLANE;
    for (int i = tid; i < 18 * 258; i += 256){
        int r = i / 258, cc = i % 258;
        int gy = y0 + r - 1, gx = cc - 1;
        float v = 0.f;
        if ((unsigned)gy < 256u && (unsigned)gx < 256u) v = src[gy * 256 + gx];
        sm[r][cc] = v;
    }
    float w[9];
    #pragma unroll
    for (int i = 0; i < 9; i++) w[i] = wdw[ch * 9 + i];
    __syncthreads();
    int x = tid;
    float* dst = g_qkv2 + (long)bc * PLANE;
    for (int yy = 0; yy < 16; yy++){
        float a = 0.f;
        #pragma unroll
        for (int dy = 0; dy < 3; dy++)
            #pragma unroll
            for (int dx = 0; dx < 3; dx++)
                a += w[dy * 3 + dx] * sm[yy + dy][x + dx];
        dst[(y0 + yy) * 256 + x] = a;
    }
}

// ------------------------- row rfft (along x), channel-paired, 16x16 -------------------------
__global__ void __launch_bounds__(256) k_rowfft(){
    __shared__ float2 zbuf[16*257];
    __shared__ float2 tw[256];
    int tid = threadIdx.x;
    int by = blockIdx.y; int b = by >> 8, y = by & 255;
    int ch0 = blockIdx.x * 32;
    build_tw256(tw, -1.f, tid);
    int f = tid >> 4, bc = tid & 15;
    const float* re = g_qkv2 + (long)(b * COUT3 + ch0 + 2*f) * PLANE + y * 256;
    const float* im = re + PLANE;
    float2 r[16];
#pragma unroll
    for (int a = 0; a < 16; a++){ int x = a*16 + bc; r[a] = make_float2(re[x], im[x]); }
    __syncthreads();                 // tw ready
    fft16r(r, -1.f);
#pragma unroll
    for (int c = 0; c < 16; c++) zbuf[(f*16 + c)*16 + bc] = cmul(r[c], tw[bc*c]);
    __syncthreads();
    int c2 = tid & 15;
    float2 q[16];
#pragma unroll
    for (int b2 = 0; b2 < 16; b2++) q[b2] = zbuf[(f*16 + c2)*16 + b2];
    __syncthreads();                 // before re-using zbuf with stride 257
    fft16r(q, -1.f);
#pragma unroll
    for (int d = 0; d < 16; d++) zbuf[f*257 + c2 + 16*d] = q[d];
    __syncthreads();
    int t = ch0 >> 6, cb = ch0 & 63;
    long base = (((long)(t*NB + b) * 256 + y) * LL) * 64 + cb;
    for (int i = tid; i < 16*129; i += 256){
        int k = i >> 4, p = i & 15;
        float2 Zk = zbuf[p*257 + k];
        float2 Zm = zbuf[p*257 + ((256 - k) & 255)];
        float4 v = make_float4(0.5f*(Zk.x + Zm.x), 0.5f*(Zk.y - Zm.y),
                               0.5f*(Zk.y + Zm.y), 0.5f*(Zm.x - Zk.x));
        *(float4*)(g_rowA + base + (long)k*64 + 2*p) = v;
    }
}

// ------------------------- column FFT (along y), 16x16 -------------------------
__global__ void __launch_bounds__(256) k_colfft(){
    __shared__ float2 zbuf[4096];
    __shared__ float2 tw[256];
    int tid = threadIdx.x;
    int gy = blockIdx.y; int tb = gy / LL, kx = gy - tb*LL;
    int cb = blockIdx.x * 16;
    build_tw256(tw, -1.f, tid);
    int bc = tid >> 4, ch = tid & 15;
    const float2* src = g_rowA + ((long)tb*256*LL + kx) * 64 + cb + ch;
    float2 r[16];
#pragma unroll
    for (int a = 0; a < 16; a++) r[a] = src[(long)(a*16 + bc) * LL * 64];
    __syncthreads();
    fft16r(r, -1.f);
#pragma unroll
    for (int c = 0; c < 16; c++) zbuf[(ch*16 + c)*16 + bc] = cmul(r[c], tw[bc*c]);
    __syncthreads();
    int c2 = tid >> 4, ch2 = tid & 15;
    float2 q[16];
#pragma unroll
    for (int b2 = 0; b2 < 16; b2++) q[b2] = zbuf[(ch2*16 + c2)*16 + b2];
    fft16r(q, -1.f);
    const float sc = 1.f/256.f;
    long ob = (long)tb*POSN*128 + (long)kx*128 + cb + ch2;
#pragma unroll
    for (int d = 0; d < 16; d++){
        int ky = c2 + 16*d;
        float* o = g_freq + ob + (long)ky*LL*128;
        o[0]  = q[d].x * sc;
        o[64] = q[d].y * sc;
    }
}

// ------------------------- gather into packed head tensors -------------------------
__global__ void __launch_bounds__(256) k_gather(){
    __shared__ float tile[64][129];
    __shared__ int sidx[64];
    int tb = blockIdx.y;
    int cc = blockIdx.x;
    int pp0 = cc * 64;
    int f = pp0 / NN2, n0 = pp0 % NN2;
    int tid = threadIdx.x;
    if (tid < 64) sidx[tid] = g_idx[pp0 + tid];
    __syncthreads();
    long fb = (long)tb * POSN * 128;
    for (int i = tid; i < 64*128; i += 256){
        int ppl = i >> 7, val = i & 127;
        tile[ppl][val] = g_freq[fb + (long)sidx[ppl]*128 + val];
    }
    __syncthreads();
    long pb = (long)tb * NHEAD * 32 * NN2;
    for (int i = tid; i < 64*128; i += 256){
        int val = i >> 6, ppl = i & 63;
        int h = val >> 4, ci = val & 15;
        int j = ci*2 + f;
        g_pack[pb + (long)(h*32 + j)*NN2 + n0 + ppl] = tile[ppl][val];
    }
}

// ------------------------- Gram + norms (split-N with atomics) -------------------------
__global__ void __launch_bounds__(256) k_gram(){
    __shared__ float qS[32][130], kS[32][130];
    int bh = blockIdx.x;
    long qb = (long)bh * 32 * NN2;
    long kb = ((long)(NB*NHEAD) + bh) * 32 * NN2;
    int tid = threadIdx.x;
    int i2 = tid >> 4, j2 = tid & 15;
    float a00 = 0.f, a01 = 0.f, a10 = 0.f, a11 = 0.f, nacc = 0.f;
    for (int tile = blockIdx.y; tile < 129; tile += gridDim.y){
        int nc = tile * 128;
        __syncthreads();
        for (int i = tid; i < 32*128; i += 256){
            int r = i >> 7, n = i & 127;
            qS[r][n] = g_pack[qb + (long)r*NN2 + nc + n];
            kS[r][n] = g_pack[kb + (long)r*NN2 + nc + n];
        }
        __syncthreads();
#pragma unroll 4
        for (int n = 0; n < 128; n++){
            float q0 = qS[i2*2][n], q1 = qS[i2*2+1][n];
            float k0 = kS[j2*2][n], k1 = kS[j2*2+1][n];
            a00 += q0*k0; a01 += q0*k1; a10 += q1*k0; a11 += q1*k1;
        }
        if (tid < 64){
            const float* s = (tid < 32) ? &qS[tid][0] : &kS[tid-32][0];
            float acc = 0.f;
#pragma unroll 4
            for (int n = 0; n < 128; n++){ float v = s[n]; acc += v*v; }
            nacc += acc;
        }
    }
    float* G = g_gram + bh * 1024;
    int i = i2*2, j = j2*2;
    atomicAdd(&G[i*32 + j],       a00);
    atomicAdd(&G[i*32 + j + 1],   a01);
    atomicAdd(&G[(i+1)*32 + j],   a10);
    atomicAdd(&G[(i+1)*32 + j+1], a11);
    if (tid < 64) atomicAdd(&g_nrm[bh*64 + tid], nacc);
}

// ------------------------- softmax1 with folded l2norm + temperature -------------------------
__global__ void k_attn(const float* __restrict__ temp){
    int bh = blockIdx.x; int h = bh & 7;
    int i = threadIdx.y, j = threadIdx.x;
    float nq = sqrtf(g_nrm[bh*64 + i]);
    float nk = sqrtf(g_nrm[bh*64 + 32 + j]);
    float sc = temp[h] / (fmaxf(nq, 1e-12f) * fmaxf(nk, 1e-12f));
    float e = expf(g_gram[bh*1024 + i*32 + j] * sc);
    float s = e;
    #pragma unroll
    for (int d = 16; d; d >>= 1) s += __shfl_xor_sync(0xffffffffu, s, d);
    g_attn[bh*1024 + i*32 + j] = e / (s + 1.f);
}

// ------------------------- O = attn * V -------------------------
__global__ void __launch_bounds__(128) k_av(){
    __shared__ float vS[32][129];
    __shared__ float aS[32][32];
    int bh = blockIdx.y;
    int n0 = blockIdx.x * 128;
    long vb = ((long)(2*NB*NHEAD) + bh) * 32 * NN2;
    int tid = threadIdx.x;
    for (int i = tid; i < 1024; i += 128) aS[i >> 5][i & 31] = g_attn[bh*1024 + i];
    for (int i = tid; i < 32*128; i += 128){
        int r = i >> 7, n = i & 127;
        vS[r][n] = g_pack[vb + (long)r*NN2 + n0 + n];
    }
    __syncthreads();
    long ob = (long)bh * 32 * NN2;
    for (int i = 0; i < 32; i++){
        float a = 0.f;
        #pragma unroll 8
        for (int j = 0; j < 32; j++) a += aS[i][j] * vS[j][tid];
        g_opack[ob + (long)i*NN2 + n0 + tid] = a;
    }
}

// ------------------------- scatter back to freq layout -------------------------
__global__ void __launch_bounds__(256) k_scatter(){
    __shared__ float tile[128][65];
    __shared__ int sidx[64];
    int b = blockIdx.y, cc = blockIdx.x;
    int pp0 = cc * 64;
    int f = pp0 / NN2, n0 = pp0 % NN2;
    int tid = threadIdx.x;
    if (tid < 64) sidx[tid] = g_idx[pp0 + tid];
    __syncthreads();
    long pb = (long)b * NHEAD * 32 * NN2;
    for (int i = tid; i < 128*64; i += 256){
        int ppl = i & 63, val = i >> 6;
        int h = val >> 4, ci = val & 15;
        tile[val][ppl] = g_opack[pb + (long)(h*32 + ci*2 + f)*NN2 + n0 + ppl];
    }
    __syncthreads();
    long ob = (long)b * POSN * 128;
    for (int i = tid; i < 128*64; i += 256){
        int val = i & 127, ppl = i >> 7;
        g_ofreq[ob + (long)sidx[ppl]*128 + val] = tile[val][ppl];
    }
}

// ------------------------- inverse column FFT (along ky), 16x16 -------------------------
__global__ void __launch_bounds__(256) k_invcol(){
    __shared__ float2 zbuf[4096];
    __shared__ float2 tw[256];
    int tid = threadIdx.x;
    int gy = blockIdx.y; int b = gy / LL, kx = gy - b*LL;
    int cb = blockIdx.x * 16;
    build_tw256(tw, 1.f, tid);
    int bc = tid >> 4, ch = tid & 15;
    const float* src = g_ofreq + (long)b*POSN*128 + (long)kx*128 + cb + ch;
    float2 r[16];
#pragma unroll
    for (int a = 0; a < 16; a++){
        const float* p = src + (long)(a*16 + bc)*LL*128;
        r[a] = make_float2(p[0], p[64]);
    }
    __syncthreads();
    fft16r(r, 1.f);
#pragma unroll
    for (int c = 0; c < 16; c++) zbuf[(ch*16 + c)*16 + bc] = cmul(r[c], tw[bc*c]);
    __syncthreads();
    int c2 = tid >> 4, ch2 = tid & 15;
    float2 q[16];
#pragma unroll
    for (int b2 = 0; b2 < 16; b2++) q[b2] = zbuf[(ch2*16 + c2)*16 + b2];
    fft16r(q, 1.f);
    long ob = ((long)b*256*LL + kx) * 64 + cb + ch2;
#pragma unroll
    for (int d = 0; d < 16; d++){
        int yo = c2 + 16*d;
        g_backT[ob + (long)yo*LL*64] = q[d];
    }
}

// ------------------------- inverse row rfft (along x), channel-paired, 16x16 -------------------------
__global__ void __launch_bounds__(256) k_invrow(){
    __shared__ float2 zbuf[16*257];
    __shared__ float2 tw[256];
    int tid = threadIdx.x;
    int by = blockIdx.y; int b = by >> 8, y = by & 255;
    int cb = blockIdx.x * 32;
    build_tw256(tw, 1.f, tid);
    long ib = ((long)b*256 + y) * LL * 64 + cb;
    for (int i = tid; i < 16*129; i += 256){
        int k = i >> 4, p = i & 15;
        float4 v = *(const float4*)(g_backT + ib + (long)k*64 + 2*p);
        float2 A = make_float2(v.x, v.y), Bv = make_float2(v.z, v.w);
        if (k == 0 || k == 128){ A.y = 0.f; Bv.y = 0.f; }
        zbuf[p*257 + k] = make_float2(A.x - Bv.y, A.y + Bv.x);
        if (k >= 1 && k <= 127)
            zbuf[p*257 + 256 - k] = make_float2(A.x + Bv.y, Bv.x - A.y);
    }
    __syncthreads();
    int f = tid >> 4, bc = tid & 15;
    float2 r[16];
#pragma unroll
    for (int a = 0; a < 16; a++) r[a] = zbuf[f*257 + a*16 + bc];
    __syncthreads();                 // done reading stride-257 region
    fft16r(r, 1.f);
#pragma unroll
    for (int c = 0; c < 16; c++) zbuf[(f*16 + c)*16 + bc] = cmul(r[c], tw[bc*c]);
    __syncthreads();
    int c2 = tid & 15;
    float2 q[16];
#pragma unroll
    for (int b2 = 0; b2 < 16; b2++) q[b2] = zbuf[(f*16 + c2)*16 + b2];
    fft16r(q, 1.f);
    const float sc = 1.f/256.f;
    float* dre = g_spat + (long)(b*CIN + cb + 2*f) * PLANE + y*256;
    float* dim = dre + PLANE;
#pragma unroll
    for (int d = 0; d < 16; d++){
        int x = c2 + 16*d;
        dre[x] = q[d].x * sc;
        dim[x] = q[d].y * sc;
    }
}

// ------------------------- launch -------------------------
extern "C" void kernel_launch(void* const* d_in, const int* in_sizes, int n_in,
                              void* d_out, int out_size) {
    const float* x      = (const float*)d_in[0];
    const float* w_qkv  = (const float*)d_in[1];
    const float* w_dw   = (const float*)d_in[2];
    const float* w_proj = (const float*)d_in[3];
    const float* temp   = (const float*)d_in[4];
    float* out = (float*)d_out;

    k_zero<<<129, 256>>>();                      // 1
    k_hist<<<129, 256>>>();                      // 2
    k_scan<<<1, 256>>>();                        // 3
    k_convqkv<<<dim3(1024, 3), 256>>>(x, w_qkv); // 4 <- ncu capture slot
    k_fill<<<64, 256>>>();                       // 5 (before k_gather; dependency safe)

    k_dwconv<<<dim3(16, NB * COUT3), 256>>>(w_dw);

    k_rowfft<<<dim3(6, NB * 256), 256>>>();
    k_colfft<<<dim3(4, 12 * LL), 256>>>();

    k_gather<<<dim3(516, 12), 256>>>();
    k_gram<<<dim3(32, 16), 256>>>();
    k_attn<<<32, dim3(32, 32)>>>(temp);
    k_av<<<dim3(129, 32), 128>>>();
    k_scatter<<<dim3(516, NB), 256>>>();

    k_invcol<<<dim3(4, NB * LL), 256>>>();
    k_invrow<<<dim3(2, NB * 256), 256>>>();

    k_convproj<<<dim3(1024, 1), 256>>>(w_proj, out);
}

// round 15
// speedup vs baseline: 1.1558x; 1.0513x over previous
#include <cuda_runtime.h>
#include <cstdint>

#define NB 4
#define CIN 64
#define COUT3 192
#define LL 129
#define POSN 33024
#define NN2 16512
#define NHEAD 8
#define NBINS 16257
#define PLANE 65536

// ------------------------- device scratch (no allocation) -------------------------
__device__ float  g_qkv [NB*COUT3*PLANE];
__device__ float  g_qkv2[NB*COUT3*PLANE];
__device__ float2 g_rowA[(long)12*256*LL*64];     // [tb][y][k][64ch] complex
__device__ float  g_freq[(long)12*POSN*128];      // [tb][pos][re64|im64]
__device__ float  g_pack[(long)12*NHEAD*32*NN2];  // [tb][h][j][n] (only v third used)
__device__ float  g_ofreq[(long)NB*POSN*128];
__device__ float2 g_backT[(long)NB*256*LL*64];    // [b][y][k][64ch] complex
__device__ float  g_spat[(long)NB*CIN*PLANE];
__device__ float  g_gram[NB*NHEAD*32*32];
__device__ float  g_nrm [NB*NHEAD*64];
__device__ float  g_attn[NB*NHEAD*32*32];
__device__ int    g_hist[NBINS];
__device__ int    g_off [NBINS];
__device__ int    g_idx [POSN];

// ------------------------- helpers -------------------------
__device__ __forceinline__ float2 cmul(float2 a, float2 b){
    return make_float2(a.x*b.x - a.y*b.y, a.x*b.y + a.y*b.x);
}

// packed f32x2 helpers
__device__ __forceinline__ unsigned long long pack2(float lo, float hi){
    unsigned long long d;
    asm("mov.b64 %0, {%1, %2};" : "=l"(d) : "f"(lo), "f"(hi));
    return d;
}
__device__ __forceinline__ unsigned long long pack2b(float v){
    unsigned long long d;
    asm("mov.b64 %0, {%1, %1};" : "=l"(d) : "f"(v));
    return d;
}
__device__ __forceinline__ void ffma2(unsigned long long& d, unsigned long long a, unsigned long long b){
    asm("fma.rn.f32x2 %0, %1, %2, %0;" : "+l"(d) : "l"(a), "l"(b));
}
__device__ __forceinline__ float2 unpack2(unsigned long long v){
    float2 r;
    asm("mov.b64 {%0, %1}, %2;" : "=f"(r.x), "=f"(r.y) : "l"(v));
    return r;
}

// 16-point radix-2 DIT FFT fully in registers. sgn=-1 forward, +1 inverse.
__device__ __forceinline__ void fft16r(float2* r, float sgn){
    float2 t;
#define SWP(a,b) { t=r[a]; r[a]=r[b]; r[b]=t; }
    SWP(1,8) SWP(2,4) SWP(3,12) SWP(5,10) SWP(7,14) SWP(11,13)
#undef SWP
    const float C[8] = {1.f, 0.92387953251f, 0.70710678119f, 0.38268343236f,
                        0.f, -0.38268343236f, -0.70710678119f, -0.92387953251f};
    const float S[8] = {0.f, 0.38268343236f, 0.70710678119f, 0.92387953251f,
                        1.f, 0.92387953251f, 0.70710678119f, 0.38268343236f};
#pragma unroll
    for (int s = 0; s < 4; s++){
        int half = 1 << s;
#pragma unroll
        for (int k = 0; k < 8; k++){
            int j = k & (half-1);
            int base = ((k>>s)<<(s+1)) + j;
            int m = j << (3-s);
            float2 w = make_float2(C[m], sgn*S[m]);
            float2 a = r[base];
            float2 b = cmul(r[base+half], w);
            r[base]      = make_float2(a.x+b.x, a.y+b.y);
            r[base+half] = make_float2(a.x-b.x, a.y-b.y);
        }
    }
}

__device__ __forceinline__ void build_tw256(float2* tw, float sgn, int tid){
    float ang = sgn * 6.283185307179586f * (float)tid / 256.0f;
    float s, c; sincosf(ang, &s, &c);
    tw[tid] = make_float2(c, s);
}

// ------------------------- permutation -------------------------
__global__ void k_zero(){
    int i = blockIdx.x * 256 + threadIdx.x;
    if (i < NBINS) g_hist[i] = 0;
    if (i < 32*1024) g_gram[i] = 0.f;
    if (i < 32*64) g_nrm[i] = 0.f;
}
__global__ void k_hist(){
    int j = blockIdx.x * 256 + threadIdx.x;
    if (j < POSN){
        int r = j / LL, l = j % LL;
        int m = (r < 128) ? r : 255 - r;
        atomicAdd(&g_hist[m * l], 1);
    }
}
__global__ void k_scan(){
    __shared__ int part[256];
    int tid = threadIdx.x;
    int s = 0;
    for (int i = 0; i < 64; i++){
        int K = tid * 64 + i;
        if (K < NBINS) s += g_hist[K];
    }
    part[tid] = s;
    __syncthreads();
    if (tid == 0){
        int run = 0;
        for (int i = 0; i < 256; i++){ int t = part[i]; part[i] = run; run += t; }
    }
    __syncthreads();
    int run = part[tid];
    for (int i = 0; i < 64; i++){
        int K = tid * 64 + i;
        if (K < NBINS){ g_off[K] = run; run += g_hist[K]; }
    }
}
__global__ void k_fill(){
    int K = blockIdx.x * 256 + threadIdx.x;
    if (K >= NBINS) return;
    int o = g_off[K];
    if (K == 0){
        for (int l = 0; l <= 128; l++) g_idx[o++] = l;
        for (int r = 1; r <= 254; r++) g_idx[o++] = r * LL;
        for (int l = 0; l <= 128; l++) g_idx[o++] = 255 * LL + l;
    } else {
        for (int v = 1; v <= 127; v++)
            if (K % v == 0){ int l = K / v; if (l <= 128) g_idx[o++] = v * LL + l; }
        for (int v = 127; v >= 1; v--)
            if (K % v == 0){ int l = K / v; if (l <= 128) g_idx[o++] = (255 - v) * LL + l; }
    }
}

// ------------------------- 1x1 conv (8oc x 8px per thread, f32x2, double-buffered) -------------------------
template<int OC>
__device__ __forceinline__ void conv_body(const float* __restrict__ x,
                                          const float* __restrict__ w,
                                          float* __restrict__ out){
    __shared__ float xS[2][8][256];
    __shared__ float wS[2][8][64];
    int p0 = blockIdx.x * 256;
    int og = blockIdx.y * 64;
    int b = p0 / PLANE; int pp = p0 % PLANE;
    int tid = threadIdx.x;
    int tx = tid & 31, ty = tid >> 5;
    unsigned long long acc[8][4];
    #pragma unroll
    for (int i = 0; i < 8; i++)
        #pragma unroll
        for (int j = 0; j < 4; j++) acc[i][j] = 0ull;

    float xr[8], wr[2];
    #pragma unroll
    for (int k = 0; k < 8; k++){
        int i = tid + k * 256;
        xr[k] = x[(long)(b * CIN + (i >> 8)) * PLANE + pp + (i & 255)];
    }
    #pragma unroll
    for (int k = 0; k < 2; k++){
        int i = tid + k * 256;
        wr[k] = w[(og + (i & 63)) * CIN + (i >> 6)];
    }
    #pragma unroll
    for (int k = 0; k < 8; k++){
        int i = tid + k * 256;
        xS[0][i >> 8][i & 255] = xr[k];
    }
    #pragma unroll
    for (int k = 0; k < 2; k++){
        int i = tid + k * 256;
        wS[0][i >> 6][i & 63] = wr[k];
    }
    __syncthreads();

    int buf = 0;
    for (int c0 = 0; c0 < 64; c0 += 8){
        bool more = (c0 + 8 < 64);
        if (more){
            #pragma unroll
            for (int k = 0; k < 8; k++){
                int i = tid + k * 256;
                xr[k] = x[(long)(b * CIN + c0 + 8 + (i >> 8)) * PLANE + pp + (i & 255)];
            }
            #pragma unroll
            for (int k = 0; k < 2; k++){
                int i = tid + k * 256;
                wr[k] = w[(og + (i & 63)) * CIN + c0 + 8 + (i >> 6)];
            }
        }
        #pragma unroll
        for (int cc = 0; cc < 8; cc++){
            float4 wv0 = *(const float4*)&wS[buf][cc][ty * 8];
            float4 wv1 = *(const float4*)&wS[buf][cc][ty * 8 + 4];
            unsigned long long wr2[8];
            wr2[0] = pack2b(wv0.x); wr2[1] = pack2b(wv0.y);
            wr2[2] = pack2b(wv0.z); wr2[3] = pack2b(wv0.w);
            wr2[4] = pack2b(wv1.x); wr2[5] = pack2b(wv1.y);
            wr2[6] = pack2b(wv1.z); wr2[7] = pack2b(wv1.w);
            float4 v0 = *(const float4*)&xS[buf][cc][tx * 8];
            float4 v1 = *(const float4*)&xS[buf][cc][tx * 8 + 4];
            unsigned long long xr2[4];
            xr2[0] = pack2(v0.x, v0.y); xr2[1] = pack2(v0.z, v0.w);
            xr2[2] = pack2(v1.x, v1.y); xr2[3] = pack2(v1.z, v1.w);
            #pragma unroll
            for (int i = 0; i < 8; i++)
                #pragma unroll
                for (int j = 0; j < 4; j++) ffma2(acc[i][j], wr2[i], xr2[j]);
        }
        if (more){
            int nb = buf ^ 1;
            #pragma unroll
            for (int k = 0; k < 8; k++){
                int i = tid + k * 256;
                xS[nb][i >> 8][i & 255] = xr[k];
            }
            #pragma unroll
            for (int k = 0; k < 2; k++){
                int i = tid + k * 256;
                wS[nb][i >> 6][i & 63] = wr[k];
            }
            __syncthreads();
            buf = nb;
        }
    }
    #pragma unroll
    for (int i = 0; i < 8; i++){
        int o = og + ty * 8 + i;
        float* dst = out + (long)(b * OC + o) * PLANE + pp + tx * 8;
        #pragma unroll
        for (int j = 0; j < 4; j++) *(float2*)(dst + 2 * j) = unpack2(acc[i][j]);
    }
}
__global__ void __launch_bounds__(256) k_convqkv(const float* __restrict__ x, const float* __restrict__ w){
    conv_body<COUT3>(x, w, g_qkv);
}
__global__ void __launch_bounds__(256) k_convproj(const float* __restrict__ w, float* __restrict__ out){
    conv_body<CIN>(g_spat, w, out);
}

// ------------------------- 3x3 depthwise conv -------------------------
__global__ void __launch_bounds__(256) k_dwconv(const float* __restrict__ wdw){
    __shared__ float sm[18][258];
    int bc = blockIdx.y;
    int ch = bc % COUT3;
    int y0 = blockIdx.x * 16;
    int tid = threadIdx.x;
    const float* src = g_qkv + (long)bc * PLANE;
    for (int i = tid; i < 18 * 258; i += 256){
        int r = i / 258, cc = i % 258;
        int gy = y0 + r - 1, gx = cc - 1;
        float v = 0.f;
        if ((unsigned)gy < 256u && (unsigned)gx < 256u) v = src[gy * 256 + gx];
        sm[r][cc] = v;
    }
    float w[9];
    #pragma unroll
    for (int i = 0; i < 9; i++) w[i] = wdw[ch * 9 + i];
    __syncthreads();
    int x = tid;
    float* dst = g_qkv2 + (long)bc * PLANE;
    for (int yy = 0; yy < 16; yy++){
        float a = 0.f;
        #pragma unroll
        for (int dy = 0; dy < 3; dy++)
            #pragma unroll
            for (int dx = 0; dx < 3; dx++)
                a += w[dy * 3 + dx] * sm[yy + dy][x + dx];
        dst[(y0 + yy) * 256 + x] = a;
    }
}

// ------------------------- row rfft (along x), channel-paired, 16x16 -------------------------
__global__ void __launch_bounds__(256) k_rowfft(){
    __shared__ float2 zbuf[16*257];
    __shared__ float2 tw[256];
    int tid = threadIdx.x;
    int by = blockIdx.y; int b = by >> 8, y = by & 255;
    int ch0 = blockIdx.x * 32;
    build_tw256(tw, -1.f, tid);
    int f = tid >> 4, bc = tid & 15;
    const float* re = g_qkv2 + (long)(b * COUT3 + ch0 + 2*f) * PLANE + y * 256;
    const float* im = re + PLANE;
    float2 r[16];
#pragma unroll
    for (int a = 0; a < 16; a++){ int x = a*16 + bc; r[a] = make_float2(re[x], im[x]); }
    __syncthreads();
    fft16r(r, -1.f);
#pragma unroll
    for (int c = 0; c < 16; c++) zbuf[(f*16 + c)*16 + bc] = cmul(r[c], tw[bc*c]);
    __syncthreads();
    int c2 = tid & 15;
    float2 q[16];
#pragma unroll
    for (int b2 = 0; b2 < 16; b2++) q[b2] = zbuf[(f*16 + c2)*16 + b2];
    __syncthreads();
    fft16r(q, -1.f);
#pragma unroll
    for (int d = 0; d < 16; d++) zbuf[f*257 + c2 + 16*d] = q[d];
    __syncthreads();
    int t = ch0 >> 6, cb = ch0 & 63;
    long base = (((long)(t*NB + b) * 256 + y) * LL) * 64 + cb;
    for (int i = tid; i < 16*129; i += 256){
        int k = i >> 4, p = i & 15;
        float2 Zk = zbuf[p*257 + k];
        float2 Zm = zbuf[p*257 + ((256 - k) & 255)];
        float4 v = make_float4(0.5f*(Zk.x + Zm.x), 0.5f*(Zk.y - Zm.y),
                               0.5f*(Zk.y + Zm.y), 0.5f*(Zm.x - Zk.x));
        *(float4*)(g_rowA + base + (long)k*64 + 2*p) = v;
    }
}

// ------------------------- column FFT (along y), 16x16 -------------------------
__global__ void __launch_bounds__(256) k_colfft(){
    __shared__ float2 zbuf[4096];
    __shared__ float2 tw[256];
    int tid = threadIdx.x;
    int gy = blockIdx.y; int tb = gy / LL, kx = gy - tb*LL;
    int cb = blockIdx.x * 16;
    build_tw256(tw, -1.f, tid);
    int bc = tid >> 4, ch = tid & 15;
    const float2* src = g_rowA + ((long)tb*256*LL + kx) * 64 + cb + ch;
    float2 r[16];
#pragma unroll
    for (int a = 0; a < 16; a++) r[a] = src[(long)(a*16 + bc) * LL * 64];
    __syncthreads();
    fft16r(r, -1.f);
#pragma unroll
    for (int c = 0; c < 16; c++) zbuf[(ch*16 + c)*16 + bc] = cmul(r[c], tw[bc*c]);
    __syncthreads();
    int c2 = tid >> 4, ch2 = tid & 15;
    float2 q[16];
#pragma unroll
    for (int b2 = 0; b2 < 16; b2++) q[b2] = zbuf[(ch2*16 + c2)*16 + b2];
    fft16r(q, -1.f);
    const float sc = 1.f/256.f;
    long ob = (long)tb*POSN*128 + (long)kx*128 + cb + ch2;
#pragma unroll
    for (int d = 0; d < 16; d++){
        int ky = c2 + 16*d;
        float* o = g_freq + ob + (long)ky*LL*128;
        o[0]  = q[d].x * sc;
        o[64] = q[d].y * sc;
    }
}

// ------------------------- gather V only into packed head tensor -------------------------
__global__ void __launch_bounds__(256) k_gather(){
    __shared__ float tile[64][129];
    __shared__ int sidx[64];
    int tb = 2 * NB + blockIdx.y;   // v tensors only
    int cc = blockIdx.x;
    int pp0 = cc * 64;
    int f = pp0 / NN2, n0 = pp0 % NN2;
    int tid = threadIdx.x;
    if (tid < 64) sidx[tid] = g_idx[pp0 + tid];
    __syncthreads();
    long fb = (long)tb * POSN * 128;
    for (int i = tid; i < 64*128; i += 256){
        int ppl = i >> 7, val = i & 127;
        tile[ppl][val] = g_freq[fb + (long)sidx[ppl]*128 + val];
    }
    __syncthreads();
    long pb = (long)tb * NHEAD * 32 * NN2;
    for (int i = tid; i < 64*128; i += 256){
        int val = i >> 6, ppl = i & 63;
        int h = val >> 4, ci = val & 15;
        int j = ci*2 + f;
        g_pack[pb + (long)(h*32 + j)*NN2 + n0 + ppl] = tile[ppl][val];
    }
}

// ------------------------- Gram + norms: gather q,k directly from g_freq -------------------------
// pack row j = 2ci+f at index n  ==  g_freq[tb][ g_idx[f*NN2+n] ][ h*16+ci ]
__global__ void __launch_bounds__(256) k_gram(){
    __shared__ float qS[2][16][132], kS[2][16][132];
    __shared__ int sidxS[2][128];
    int bh = blockIdx.x;
    int b = bh >> 3, h = bh & 7;
    long fq = (long)b * POSN * 128;
    long fk = (long)(NB + b) * POSN * 128;
    int hbase = h * 16;
    int tid = threadIdx.x;
    int i2 = tid >> 4, j2 = tid & 15;
    float a00 = 0.f, a01 = 0.f, a10 = 0.f, a11 = 0.f, nacc = 0.f;
    for (int tile = blockIdx.y; tile < 129; tile += gridDim.y){
        int nc = tile * 128;
        __syncthreads();
        {
            int f = tid >> 7, n = tid & 127;
            sidxS[f][n] = g_idx[f * NN2 + nc + n];
        }
        __syncthreads();
        for (int i = tid; i < 2*16*128; i += 256){
            int ci = i & 15, n = (i >> 4) & 127, f = i >> 11;
            long prow = (long)sidxS[f][n] * 128 + hbase + ci;
            qS[f][ci][n] = g_freq[fq + prow];
            kS[f][ci][n] = g_freq[fk + prow];
        }
        __syncthreads();
#pragma unroll 4
        for (int n = 0; n < 128; n++){
            float q0 = qS[0][i2][n], q1 = qS[1][i2][n];
            float k0 = kS[0][j2][n], k1 = kS[1][j2][n];
            a00 += q0*k0; a01 += q0*k1; a10 += q1*k0; a11 += q1*k1;
        }
        if (tid < 64){
            int j = (tid < 32) ? tid : tid - 32;
            const float* s = (tid < 32) ? &qS[j & 1][j >> 1][0] : &kS[j & 1][j >> 1][0];
            float acc = 0.f;
#pragma unroll 4
            for (int n = 0; n < 128; n++){ float v = s[n]; acc += v*v; }
            nacc += acc;
        }
    }
    float* G = g_gram + bh * 1024;
    int i = i2*2, j = j2*2;
    atomicAdd(&G[i*32 + j],       a00);
    atomicAdd(&G[i*32 + j + 1],   a01);
    atomicAdd(&G[(i+1)*32 + j],   a10);
    atomicAdd(&G[(i+1)*32 + j+1], a11);
    if (tid < 64) atomicAdd(&g_nrm[bh*64 + tid], nacc);
}

// ------------------------- softmax1 with folded l2norm + temperature -------------------------
__global__ void k_attn(const float* __restrict__ temp){
    int bh = blockIdx.x; int h = bh & 7;
    int i = threadIdx.y, j = threadIdx.x;
    float nq = sqrtf(g_nrm[bh*64 + i]);
    float nk = sqrtf(g_nrm[bh*64 + 32 + j]);
    float sc = temp[h] / (fmaxf(nq, 1e-12f) * fmaxf(nk, 1e-12f));
    float e = expf(g_gram[bh*1024 + i*32 + j] * sc);
    float s = e;
    #pragma unroll
    for (int d = 16; d; d >>= 1) s += __shfl_xor_sync(0xffffffffu, s, d);
    g_attn[bh*1024 + i*32 + j] = e / (s + 1.f);
}

// ------------------------- O = attn * V, written scattered directly into g_ofreq -------------------------
// o row i = 2ci+f at index n -> g_ofreq[b][ g_idx[f*NN2+n] ][ h*16+ci ]
__global__ void __launch_bounds__(128) k_av(){
    __shared__ float vS[32][129];
    __shared__ float aS[32][32];
    __shared__ int sidxS[2][128];
    __shared__ float oT[128][33];
    int bh = blockIdx.y;
    int b = bh >> 3, h = bh & 7;
    int n0 = blockIdx.x * 128;
    long vb = ((long)(2*NB*NHEAD) + bh) * 32 * NN2;
    int tid = threadIdx.x;
    sidxS[0][tid] = g_idx[n0 + tid];
    sidxS[1][tid] = g_idx[NN2 + n0 + tid];
    for (int i = tid; i < 1024; i += 128) aS[i >> 5][i & 31] = g_attn[bh*1024 + i];
    for (int i = tid; i < 32*128; i += 128){
        int r = i >> 7, n = i & 127;
        vS[r][n] = g_pack[vb + (long)r*NN2 + n0 + n];
    }
    __syncthreads();
    for (int i = 0; i < 32; i++){
        float a = 0.f;
        #pragma unroll 8
        for (int j = 0; j < 32; j++) a += aS[i][j] * vS[j][tid];
        oT[tid][i] = a;
    }
    __syncthreads();
    long ob = (long)b * POSN * 128;
    for (int t = tid; t < 256; t += 128){
        int f = t & 1, n = t >> 1;
        float* dst = g_ofreq + ob + (long)sidxS[f][n] * 128 + h * 16;
        float4 v0 = make_float4(oT[n][0+f],  oT[n][2+f],  oT[n][4+f],  oT[n][6+f]);
        float4 v1 = make_float4(oT[n][8+f],  oT[n][10+f], oT[n][12+f], oT[n][14+f]);
        float4 v2 = make_float4(oT[n][16+f], oT[n][18+f], oT[n][20+f], oT[n][22+f]);
        float4 v3 = make_float4(oT[n][24+f], oT[n][26+f], oT[n][28+f], oT[n][30+f]);
        *(float4*)(dst)      = v0;
        *(float4*)(dst + 4)  = v1;
        *(float4*)(dst + 8)  = v2;
        *(float4*)(dst + 12) = v3;
    }
}

// ------------------------- inverse column FFT (along ky), 16x16 -------------------------
__global__ void __launch_bounds__(256) k_invcol(){
    __shared__ float2 zbuf[4096];
    __shared__ float2 tw[256];
    int tid = threadIdx.x;
    int gy = blockIdx.y; int b = gy / LL, kx = gy - b*LL;
    int cb = blockIdx.x * 16;
    build_tw256(tw, 1.f, tid);
    int bc = tid >> 4, ch = tid & 15;
    const float* src = g_ofreq + (long)b*POSN*128 + (long)kx*128 + cb + ch;
    float2 r[16];
#pragma unroll
    for (int a = 0; a < 16; a++){
        const float* p = src + (long)(a*16 + bc)*LL*128;
        r[a] = make_float2(p[0], p[64]);
    }
    __syncthreads();
    fft16r(r, 1.f);
#pragma unroll
    for (int c = 0; c < 16; c++) zbuf[(ch*16 + c)*16 + bc] = cmul(r[c], tw[bc*c]);
    __syncthreads();
    int c2 = tid >> 4, ch2 = tid & 15;
    float2 q[16];
#pragma unroll
    for (int b2 = 0; b2 < 16; b2++) q[b2] = zbuf[(ch2*16 + c2)*16 + b2];
    fft16r(q, 1.f);
    long ob = ((long)b*256*LL + kx) * 64 + cb + ch2;
#pragma unroll
    for (int d = 0; d < 16; d++){
        int yo = c2 + 16*d;
        g_backT[ob + (long)yo*LL*64] = q[d];
    }
}

// ------------------------- inverse row rfft (along x), channel-paired, 16x16 -------------------------
__global__ void __launch_bounds__(256) k_invrow(){
    __shared__ float2 zbuf[16*257];
    __shared__ float2 tw[256];
    int tid = threadIdx.x;
    int by = blockIdx.y; int b = by >> 8, y = by & 255;
    int cb = blockIdx.x * 32;
    build_tw256(tw, 1.f, tid);
    long ib = ((long)b*256 + y) * LL * 64 + cb;
    for (int i = tid; i < 16*129; i += 256){
        int k = i >> 4, p = i & 15;
        float4 v = *(const float4*)(g_backT + ib + (long)k*64 + 2*p);
        float2 A = make_float2(v.x, v.y), Bv = make_float2(v.z, v.w);
        if (k == 0 || k == 128){ A.y = 0.f; Bv.y = 0.f; }
        zbuf[p*257 + k] = make_float2(A.x - Bv.y, A.y + Bv.x);
        if (k >= 1 && k <= 127)
            zbuf[p*257 + 256 - k] = make_float2(A.x + Bv.y, Bv.x - A.y);
    }
    __syncthreads();
    int f = tid >> 4, bc = tid & 15;
    float2 r[16];
#pragma unroll
    for (int a = 0; a < 16; a++) r[a] = zbuf[f*257 + a*16 + bc];
    __syncthreads();
    fft16r(r, 1.f);
#pragma unroll
    for (int c = 0; c < 16; c++) zbuf[(f*16 + c)*16 + bc] = cmul(r[c], tw[bc*c]);
    __syncthreads();
    int c2 = tid & 15;
    float2 q[16];
#pragma unroll
    for (int b2 = 0; b2 < 16; b2++) q[b2] = zbuf[(f*16 + c2)*16 + b2];
    fft16r(q, 1.f);
    const float sc = 1.f/256.f;
    float* dre = g_spat + (long)(b*CIN + cb + 2*f) * PLANE + y*256;
    float* dim = dre + PLANE;
#pragma unroll
    for (int d = 0; d < 16; d++){
        int x = c2 + 16*d;
        dre[x] = q[d].x * sc;
        dim[x] = q[d].y * sc;
    }
}

// ------------------------- launch -------------------------
extern "C" void kernel_launch(void* const* d_in, const int* in_sizes, int n_in,
                              void* d_out, int out_size) {
    const float* x      = (const float*)d_in[0];
    const float* w_qkv  = (const float*)d_in[1];
    const float* w_dw   = (const float*)d_in[2];
    const float* w_proj = (const float*)d_in[3];
    const float* temp   = (const float*)d_in[4];
    float* out = (float*)d_out;

    k_zero<<<129, 256>>>();                      // 1
    k_hist<<<129, 256>>>();                      // 2
    k_scan<<<1, 256>>>();                        // 3
    k_convqkv<<<dim3(1024, 3), 256>>>(x, w_qkv); // 4 <- ncu capture slot
    k_fill<<<64, 256>>>();                       // 5

    k_dwconv<<<dim3(16, NB * COUT3), 256>>>(w_dw);

    k_rowfft<<<dim3(6, NB * 256), 256>>>();
    k_colfft<<<dim3(4, 12 * LL), 256>>>();

    k_gather<<<dim3(516, NB), 256>>>();          // v only
    k_gram<<<dim3(32, 16), 256>>>();
    k_attn<<<32, dim3(32, 32)>>>(temp);
    k_av<<<dim3(129, 32), 128>>>();

    k_invcol<<<dim3(4, NB * LL), 256>>>();
    k_invrow<<<dim3(2, NB * 256), 256>>>();

    k_convproj<<<dim3(1024, 1), 256>>>(w_proj, out);
}